// round 11
// baseline (speedup 1.0000x reference)
#include <cuda_runtime.h>
#include <cuda_fp16.h>
#include <math.h>
#include <cstdint>

#define NN    4096
#define NNZT  65536
#define ELLW  64

// ---------------- scratch (device globals) ----------------
__device__ int   g_len[2][NN];
__device__ int2  g_ell[2][NN * ELLW];

// fp32 canonical
__device__ float g_z[5][NN * 512];        // z0..z4, layout [n][o*32+b]
__device__ float g_theta[NN * 512];

// fp16 mirrors
__device__ __half g_x0h [NN * 512];
__device__ __half g_xs1h[NN * 512];
__device__ __half g_xs2h[NN * 512];
__device__ __half g_xs3h[NN * 512];
__device__ __half g_xs4h[NN * 512];
__device__ __half g_z2h [NN * 512];
__device__ __half g_z4h [NN * 512];
__device__ __half g_p1h [NN * 512];
__device__ __half g_p2h [NN * 512];

__device__ __forceinline__ const __half* hsel(int id) {
    switch (id) {
        case 0: return g_x0h;  case 1: return g_xs1h; case 2: return g_xs2h;
        case 3: return g_xs3h; case 4: return g_xs4h; case 5: return g_z2h;
        case 6: return g_z4h;  case 7: return g_p1h;  default: return g_p2h;
    }
}
__device__ __forceinline__ __half* hsel_w(int id) {
    switch (id) {
        case 1: return g_xs1h; case 2: return g_xs2h; case 3: return g_xs3h;
        case 4: return g_xs4h; case 7: return g_p1h;  default: return g_p2h;
    }
}
__device__ __forceinline__ const float* fsel(int id) {
    return (id == 0) ? g_z[1] : g_z[3];
}

// ---------------- helpers ----------------
__device__ __forceinline__ float4 ldh4(const uint2* p) {
    uint2 g = __ldg(p);
    __half2 a = *(__half2*)&g.x, b = *(__half2*)&g.y;
    float2 f0 = __half22float2(a), f1 = __half22float2(b);
    return make_float4(f0.x, f0.y, f1.x, f1.y);
}
__device__ __forceinline__ uint2 f4toh(float4 v) {
    __half2 a = __floats2half2_rn(v.x, v.y);
    __half2 b = __floats2half2_rn(v.z, v.w);
    uint2 r;
    r.x = *(unsigned int*)&a;
    r.y = *(unsigned int*)&b;
    return r;
}
__device__ __forceinline__ float tanh_ap(float x) {
    float r;
    asm("tanh.approx.f32 %0, %1;" : "=f"(r) : "f"(x));
    return r;
}
__device__ __forceinline__ void mma16816(float* c, uint32_t a0, uint32_t a1, uint32_t a2, uint32_t a3,
                                         uint32_t b0, uint32_t b1) {
    asm volatile("mma.sync.aligned.m16n8k16.row.col.f32.f16.f16.f32 "
        "{%0,%1,%2,%3}, {%4,%5,%6,%7}, {%8,%9}, {%0,%1,%2,%3};"
        : "+f"(c[0]), "+f"(c[1]), "+f"(c[2]), "+f"(c[3])
        : "r"(a0), "r"(a1), "r"(a2), "r"(a3), "r"(b0), "r"(b1));
}

// ---------------- transpose y -> x0h [n][f*32+b]; zero g_len ----------------
__global__ void k_transpose(const float* __restrict__ y) {
    __shared__ float s[512];
    int n = blockIdx.x, t = threadIdx.x;
    if (t < 2) g_len[t][n] = 0;
    int b = t >> 4, f = t & 15;
    s[f * 32 + b] = y[b * (NN * 16) + n * 16 + f];
    __syncthreads();
    if (t < 256)
        ((__half2*)g_x0h)[n * 256 + t] = __floats2half2_rn(s[2 * t], s[2 * t + 1]);
}

// ---------------- ELL build ----------------
__global__ void k_scat(const int* __restrict__ r1, const int* __restrict__ c1, const float* __restrict__ v1,
                       const int* __restrict__ r2, const int* __restrict__ c2, const float* __restrict__ v2) {
    int gi = blockIdx.x * blockDim.x + threadIdx.x;
    int sup = gi >= NNZT;
    int e = sup ? gi - NNZT : gi;
    if (gi < 2 * NNZT) {
        const int*   r = sup ? r2 : r1;
        const int*   c = sup ? c2 : c1;
        const float* v = sup ? v2 : v1;
        int row = __ldg(&r[e]);
        int p = atomicAdd(&g_len[sup][row], 1);
        if (p < ELLW) g_ell[sup][row * ELLW + p] = make_int2(__ldg(&c[e]), __float_as_int(__ldg(&v[e])));
    }
}

// ---------------- dual-job half SpMM: out = al*(S@hsrc) + be*add ----------------
// add: fp32 buffer (adf>=0) or fp16 buffer (adh>=0) or none
__global__ __launch_bounds__(128) void k_spmm2(
        int hA, int adfA, int adhA, float alA, float beA, int oA,
        int hB, int adfB, int adhB, float alB, float beB, int oB) {
    __shared__ int2 se[ELLW];
    int unit = blockIdx.x >> 12;
    int n = blockIdx.x & (NN - 1);
    int hid = unit ? hB : hA;
    int adf = unit ? adfB : adfA;
    int adh = unit ? adhB : adhA;
    float al = unit ? alB : alA;
    float be = unit ? beB : beA;
    int oid = unit ? oB : oA;

    int cnt = g_len[unit][n]; if (cnt > ELLW) cnt = ELLW;
    if (threadIdx.x < cnt) se[threadIdx.x] = __ldg(&g_ell[unit][n * ELLW + threadIdx.x]);
    __syncthreads();

    int j = threadIdx.x;
    const uint2* __restrict__ x = (const uint2*)hsel(hid);
    float ax = 0.f, ay = 0.f, az = 0.f, aw = 0.f;
    int i = 0;
    for (; i + 4 <= cnt; i += 4) {
        int2 e0 = se[i], e1 = se[i + 1], e2 = se[i + 2], e3 = se[i + 3];
        float4 x0 = ldh4(&x[e0.x * 128 + j]);
        float4 x1 = ldh4(&x[e1.x * 128 + j]);
        float4 x2 = ldh4(&x[e2.x * 128 + j]);
        float4 x3 = ldh4(&x[e3.x * 128 + j]);
        float v0 = __int_as_float(e0.y), v1 = __int_as_float(e1.y);
        float v2 = __int_as_float(e2.y), v3 = __int_as_float(e3.y);
        ax += v0 * x0.x; ay += v0 * x0.y; az += v0 * x0.z; aw += v0 * x0.w;
        ax += v1 * x1.x; ay += v1 * x1.y; az += v1 * x1.z; aw += v1 * x1.w;
        ax += v2 * x2.x; ay += v2 * x2.y; az += v2 * x2.z; aw += v2 * x2.w;
        ax += v3 * x3.x; ay += v3 * x3.y; az += v3 * x3.z; aw += v3 * x3.w;
    }
    for (; i < cnt; ++i) {
        int2 ed = se[i];
        float v = __int_as_float(ed.y);
        float4 xv = ldh4(&x[ed.x * 128 + j]);
        ax += v * xv.x; ay += v * xv.y; az += v * xv.z; aw += v * xv.w;
    }

    float4 r = make_float4(al * ax, al * ay, al * az, al * aw);
    if (adf >= 0) {
        float4 a = __ldg(&((const float4*)fsel(adf))[n * 128 + j]);
        r.x += be * a.x; r.y += be * a.y; r.z += be * a.z; r.w += be * a.w;
    } else if (adh >= 0) {
        float4 a = ldh4(&((const uint2*)hsel(adh))[n * 128 + j]);
        r.x += be * a.x; r.y += be * a.y; r.z += be * a.z; r.w += be * a.w;
    }
    ((uint2*)hsel_w(oid))[n * 128 + j] = f4toh(r);
}

// ---------------- slim HMMA kernel: 4 nodes per block, 256 threads ----------------
// dyn smem (halves): sA 128x84 (21504B) | sW 80x84 (13440B) | sC 128x68 (17408B) | sWo 80x68 (10880B)
#define OFF_A   0
#define OFF_W   21504
#define OFF_C   34944
#define OFF_WO  52352
#define SM_TOT  63232
#define STA 84
#define STW 84
#define STC 68
#define STO 68

__global__ __launch_bounds__(256, 3) void k_mma(const float* __restrict__ Wt,
                                                const float* __restrict__ Wh,
                                                const float* __restrict__ Wo,
                                                const float* __restrict__ blat,
                                                const float* __restrict__ bhid) {
    extern __shared__ __align__(16) char dsm[];
    __half* sA   = (__half*)(dsm + OFF_A);
    __half* sW   = (__half*)(dsm + OFF_W);
    __half* sC   = (__half*)(dsm + OFF_C);
    __half* sWo  = (__half*)(dsm + OFF_WO);

    int tid = threadIdx.x;
    int n0 = blockIdx.x * 4;

    // stage sA: 5 mirrors -> [row][k] (k = f*5+m), coalesced loads + scatter stores
    for (int e = tid; e < 2560; e += 256) {
        int m = e >> 9, idx = e & 511;
        int nd = idx >> 7, j = idx & 127;
        const __half* src = hsel(m);      // ids 0..4 = x0h, xs1h, xs2h, xs3h, xs4h
        uint2 gv = __ldg((const uint2*)&src[(n0 + nd) * 512 + j * 4]);
        __half h[4];
        *(uint2*)h = gv;
        int f = j >> 3, b0 = (j & 7) * 4;
        int k = f * 5 + m;
        int row = nd * 32 + b0;
        sA[(row + 0) * STA + k] = h[0];
        sA[(row + 1) * STA + k] = h[1];
        sA[(row + 2) * STA + k] = h[2];
        sA[(row + 3) * STA + k] = h[3];
    }
    // stage W^T [o][k]
    for (int e = tid; e < 6400; e += 256) {
        int o = e % 80, k = e / 80;
        float w = (o < 16) ? Wt[k * 16 + o] : Wh[k * 64 + (o - 16)];
        sW[o * STW + k] = __float2half(w);
    }
    // stage Wo^T [p][u]
    for (int e = tid; e < 5120; e += 256) {
        int p = e % 80, u = e / 80;
        sWo[p * STO + u] = __float2half(Wo[u * 80 + p]);
    }
    __syncthreads();

    int w = tid >> 5, t = tid & 31;
    int g = t >> 2, q = t & 3;
    int rowA = w * 16 + g;
    const __half* aBase = sA + rowA * STA;

    // GEMM1: C[128x80] = A[128x80] @ W^T, fp32 accum
    {
        float acc[10][4];
#pragma unroll
        for (int nt = 0; nt < 10; nt++)
            for (int p = 0; p < 4; p++) acc[nt][p] = 0.f;
#pragma unroll
        for (int kt = 0; kt < 5; kt++) {
            int k0 = kt * 16 + q * 2;
            uint32_t a0 = *(const uint32_t*)(aBase + k0);
            uint32_t a1 = *(const uint32_t*)(aBase + 8 * STA + k0);
            uint32_t a2 = *(const uint32_t*)(aBase + k0 + 8);
            uint32_t a3 = *(const uint32_t*)(aBase + 8 * STA + k0 + 8);
#pragma unroll
            for (int nt = 0; nt < 10; nt++) {
                const __half* bb = sW + (nt * 8 + g) * STW + k0;
                uint32_t b0 = *(const uint32_t*)bb;
                uint32_t b1 = *(const uint32_t*)(bb + 8);
                mma16816(acc[nt], a0, a1, a2, a3, b0, b1);
            }
        }
        // epilogue 1
#pragma unroll
        for (int nt = 0; nt < 10; nt++) {
            int o = nt * 8 + q * 2;
            if (o < 16) {
                float bl0 = blat[o], bl1 = blat[o + 1];
#pragma unroll
                for (int half = 0; half < 2; half++) {
                    int row = rowA + half * 8;
                    int n = n0 + (row >> 5), b = row & 31;
                    float v0 = acc[nt][half * 2]     + bl0;
                    float v1 = acc[nt][half * 2 + 1] + bl1;
                    g_theta[n * 512 + o * 32 + b]       = 0.5f + 0.5f * tanh_ap(0.5f * v0);
                    g_theta[n * 512 + (o + 1) * 32 + b] = 0.5f + 0.5f * tanh_ap(0.5f * v1);
                }
            } else {
                int u = o - 16;
                float bh0 = bhid[u], bh1 = bhid[u + 1];
#pragma unroll
                for (int half = 0; half < 2; half++) {
                    int row = rowA + half * 8;
                    __half2 hv = __floats2half2_rn(tanh_ap(acc[nt][half * 2] + bh0),
                                                   tanh_ap(acc[nt][half * 2 + 1] + bh1));
                    *(uint32_t*)(sC + row * STC + u) = *(uint32_t*)&hv;
                }
            }
        }
    }
    __syncthreads();

    // GEMM2: Z[128x80] = C1[128x64] @ Wo^T
    {
        const __half* cBase = sC + rowA * STC;
        float acc[10][4];
#pragma unroll
        for (int nt = 0; nt < 10; nt++)
            for (int p = 0; p < 4; p++) acc[nt][p] = 0.f;
#pragma unroll
        for (int kt = 0; kt < 4; kt++) {
            int k0 = kt * 16 + q * 2;
            uint32_t a0 = *(const uint32_t*)(cBase + k0);
            uint32_t a1 = *(const uint32_t*)(cBase + 8 * STC + k0);
            uint32_t a2 = *(const uint32_t*)(cBase + k0 + 8);
            uint32_t a3 = *(const uint32_t*)(cBase + 8 * STC + k0 + 8);
#pragma unroll
            for (int nt = 0; nt < 10; nt++) {
                const __half* bb = sWo + (nt * 8 + g) * STO + k0;
                uint32_t b0 = *(const uint32_t*)bb;
                uint32_t b1 = *(const uint32_t*)(bb + 8);
                mma16816(acc[nt], a0, a1, a2, a3, b0, b1);
            }
        }
        // epilogue 2: z[m][n][o*32+b] (+ mirrors m=2,4)
#pragma unroll
        for (int nt = 0; nt < 10; nt++) {
            int p = nt * 8 + q * 2;
            int m = p >> 4, o = p & 15;
            float* zm = g_z[m];
#pragma unroll
            for (int half = 0; half < 2; half++) {
                int row = rowA + half * 8;
                int n = n0 + (row >> 5), b = row & 31;
                float v0 = acc[nt][half * 2], v1 = acc[nt][half * 2 + 1];
                int i0 = n * 512 + o * 32 + b;
                int i1 = n * 512 + (o + 1) * 32 + b;
                zm[i0] = v0; zm[i1] = v1;
                if (m == 2) { g_z2h[i0] = __float2half(v0); g_z2h[i1] = __float2half(v1); }
                else if (m == 4) { g_z4h[i0] = __float2half(v0); g_z4h[i1] = __float2half(v1); }
            }
        }
    }
}

// ---------------- final: S1@p1h + S2@p2h + Z0 - Z2 - Z4 + b -> -theta*tanh ----------------
__global__ __launch_bounds__(128) void k_final(const float* __restrict__ blat, float* __restrict__ out) {
    __shared__ int2 se1[ELLW], se2[ELLW];
    __shared__ float st[512];
    int n = blockIdx.x, j = threadIdx.x;

    int c1n = g_len[0][n]; if (c1n > ELLW) c1n = ELLW;
    int c2n = g_len[1][n]; if (c2n > ELLW) c2n = ELLW;
    if (j < c1n) se1[j] = __ldg(&g_ell[0][n * ELLW + j]);
    else if (j >= 64 && j - 64 < c2n) se2[j - 64] = __ldg(&g_ell[1][n * ELLW + j - 64]);
    __syncthreads();

    const uint2* __restrict__ xp1 = (const uint2*)g_p1h;
    const uint2* __restrict__ xp2 = (const uint2*)g_p2h;
    float ax = 0.f, ay = 0.f, az = 0.f, aw = 0.f;

    int i = 0;
    for (; i + 2 <= c1n; i += 2) {
        int2 ea = se1[i], eb = se1[i + 1];
        float4 x0 = ldh4(&xp1[ea.x * 128 + j]);
        float4 x1 = ldh4(&xp1[eb.x * 128 + j]);
        float v0 = __int_as_float(ea.y), v1 = __int_as_float(eb.y);
        ax += v0 * x0.x; ay += v0 * x0.y; az += v0 * x0.z; aw += v0 * x0.w;
        ax += v1 * x1.x; ay += v1 * x1.y; az += v1 * x1.z; aw += v1 * x1.w;
    }
    for (; i < c1n; ++i) {
        int2 ed = se1[i]; float v = __int_as_float(ed.y);
        float4 xv = ldh4(&xp1[ed.x * 128 + j]);
        ax += v * xv.x; ay += v * xv.y; az += v * xv.z; aw += v * xv.w;
    }
    i = 0;
    for (; i + 2 <= c2n; i += 2) {
        int2 ea = se2[i], eb = se2[i + 1];
        float4 x0 = ldh4(&xp2[ea.x * 128 + j]);
        float4 x1 = ldh4(&xp2[eb.x * 128 + j]);
        float v0 = __int_as_float(ea.y), v1 = __int_as_float(eb.y);
        ax += v0 * x0.x; ay += v0 * x0.y; az += v0 * x0.z; aw += v0 * x0.w;
        ax += v1 * x1.x; ay += v1 * x1.y; az += v1 * x1.z; aw += v1 * x1.w;
    }
    for (; i < c2n; ++i) {
        int2 ed = se2[i]; float v = __int_as_float(ed.y);
        float4 xv = ldh4(&xp2[ed.x * 128 + j]);
        ax += v * xv.x; ay += v * xv.y; az += v * xv.z; aw += v * xv.w;
    }

    int idx = n * 128 + j;
    float4 t0 = ((const float4*)g_z[0])[idx];
    float4 t2 = ((const float4*)g_z[2])[idx];
    float4 t4 = ((const float4*)g_z[4])[idx];
    float4 tt = ((const float4*)g_theta)[idx];

    int o = j >> 3;
    float bl = blat[o];
    float4 r;
    r.x = -tt.x * tanh_ap(ax + t0.x - t2.x - t4.x + bl);
    r.y = -tt.y * tanh_ap(ay + t0.y - t2.y - t4.y + bl);
    r.z = -tt.z * tanh_ap(az + t0.z - t2.z - t4.z + bl);
    r.w = -tt.w * tanh_ap(aw + t0.w - t2.w - t4.w + bl);
    ((float4*)st)[j] = r;
    __syncthreads();

    int b = j >> 2, qo = j & 3;
    float4 w;
    w.x = st[(qo * 4 + 0) * 32 + b];
    w.y = st[(qo * 4 + 1) * 32 + b];
    w.z = st[(qo * 4 + 2) * 32 + b];
    w.w = st[(qo * 4 + 3) * 32 + b];
    ((float4*)(out + b * (NN * 16) + n * 16))[qo] = w;
}

// ---------------- host launcher ----------------
extern "C" void kernel_launch(void* const* d_in, const int* in_sizes, int n_in,
                              void* d_out, int out_size) {
    (void)in_sizes; (void)n_in; (void)out_size;
    const float* y    = (const float*)d_in[1];
    const float* Wt   = (const float*)d_in[2];
    const float* blat = (const float*)d_in[3];
    const float* Wh   = (const float*)d_in[4];
    const float* bhid = (const float*)d_in[5];
    const float* Wo   = (const float*)d_in[6];
    const int*   r1   = (const int*)d_in[7];
    const int*   c1   = (const int*)d_in[8];
    const float* v1   = (const float*)d_in[9];
    const int*   r2   = (const int*)d_in[10];
    const int*   c2   = (const int*)d_in[11];
    const float* v2   = (const float*)d_in[12];
    float* out = (float*)d_out;

    cudaFuncSetAttribute(k_mma, cudaFuncAttributeMaxDynamicSharedMemorySize, SM_TOT);

    k_transpose<<<NN, 512>>>(y);                                  // x0h ; zero g_len
    k_scat<<<2 * NNZT / 512, 512>>>(r1, c1, v1, r2, c2, v2);      // ELL both supports

    // hop1: xs1h = S1@x0h ; xs3h = S2@x0h
    k_spmm2<<<2 * NN, 128>>>(0, -1, -1, 1.f, 0.f, 1,   0, -1, -1, 1.f, 0.f, 3);
    // hop2: xs2h = 2*S1@xs1h - x0h ; xs4h = 2*S2@xs3h - x0h   (profiled slot)
    k_spmm2<<<2 * NN, 128>>>(1, -1, 0, 2.f, -1.f, 2,   3, -1, 0, 2.f, -1.f, 4);

    // slim HMMA kernel: theta/c1 GEMM + Z projection
    k_mma<<<NN / 4, 256, SM_TOT>>>(Wt, Wh, Wo, blat, bhid);

    // p1h = Z1 + 2*(S1@z2h) ; p2h = Z3 + 2*(S2@z4h)
    k_spmm2<<<2 * NN, 128>>>(5, 0, -1, 2.f, 1.f, 7,   6, 1, -1, 2.f, 1.f, 8);

    // final: second-hop gathers + combine + tanh + gate + transposed store
    k_final<<<NN, 128>>>(blat, out);
}

// round 12
// speedup vs baseline: 1.0753x; 1.0753x over previous
#include <cuda_runtime.h>
#include <cuda_fp16.h>
#include <math.h>
#include <cstdint>

#define NN    4096
#define NNZT  65536
#define ELLW  64

// ---------------- scratch (device globals) ----------------
__device__ int   g_len[2][NN];            // starts 0 (static); k_final re-zeroes
__device__ int2  g_ell[2][NN * ELLW];     // (col, val as duplicated half2)

// fp32 canonical
__device__ float g_z[5][NN * 512];        // z0..z4, layout [n][o*32+b]
__device__ float g_theta[NN * 512];

// fp16 mirrors
__device__ __half g_x0h [NN * 512];
__device__ __half g_xs1h[NN * 512];
__device__ __half g_xs2h[NN * 512];
__device__ __half g_xs3h[NN * 512];
__device__ __half g_xs4h[NN * 512];
__device__ __half g_z2h [NN * 512];
__device__ __half g_z4h [NN * 512];
__device__ __half g_p1h [NN * 512];
__device__ __half g_p2h [NN * 512];

__device__ __forceinline__ const __half* hsel(int id) {
    switch (id) {
        case 0: return g_x0h;  case 1: return g_xs1h; case 2: return g_xs2h;
        case 3: return g_xs3h; case 4: return g_xs4h; case 5: return g_z2h;
        case 6: return g_z4h;  case 7: return g_p1h;  default: return g_p2h;
    }
}
__device__ __forceinline__ __half* hsel_w(int id) {
    switch (id) {
        case 1: return g_xs1h; case 2: return g_xs2h; case 3: return g_xs3h;
        case 4: return g_xs4h; case 7: return g_p1h;  default: return g_p2h;
    }
}
__device__ __forceinline__ const float* fsel(int id) {
    return (id == 0) ? g_z[1] : g_z[3];
}

// ---------------- helpers ----------------
__device__ __forceinline__ __half2 h2b(uint32_t u) { return *(__half2*)&u; }
__device__ __forceinline__ float4 ldh4(const uint2* p) {
    uint2 g = __ldg(p);
    float2 f0 = __half22float2(h2b(g.x)), f1 = __half22float2(h2b(g.y));
    return make_float4(f0.x, f0.y, f1.x, f1.y);
}
__device__ __forceinline__ uint2 f4toh(float4 v) {
    __half2 a = __floats2half2_rn(v.x, v.y);
    __half2 b = __floats2half2_rn(v.z, v.w);
    uint2 r;
    r.x = *(unsigned int*)&a;
    r.y = *(unsigned int*)&b;
    return r;
}
__device__ __forceinline__ float tanh_ap(float x) {
    float r;
    asm("tanh.approx.f32 %0, %1;" : "=f"(r) : "f"(x));
    return r;
}
__device__ __forceinline__ void mma16816(float* c, uint32_t a0, uint32_t a1, uint32_t a2, uint32_t a3,
                                         uint32_t b0, uint32_t b1) {
    asm volatile("mma.sync.aligned.m16n8k16.row.col.f32.f16.f16.f32 "
        "{%0,%1,%2,%3}, {%4,%5,%6,%7}, {%8,%9}, {%0,%1,%2,%3};"
        : "+f"(c[0]), "+f"(c[1]), "+f"(c[2]), "+f"(c[3])
        : "r"(a0), "r"(a1), "r"(a2), "r"(a3), "r"(b0), "r"(b1));
}

// 4-edge half2 gather step: acc += sum of 4 gathered rows * half2 weights (fp16 inner, fp32 flush)
__device__ __forceinline__ void gather4(const uint2* __restrict__ x, const int2* se, int i, int j,
                                        float& ax, float& ay, float& az, float& aw) {
    int2 e0 = se[i], e1 = se[i + 1], e2 = se[i + 2], e3 = se[i + 3];
    uint2 g0 = __ldg(&x[e0.x * 128 + j]);
    uint2 g1 = __ldg(&x[e1.x * 128 + j]);
    uint2 g2 = __ldg(&x[e2.x * 128 + j]);
    uint2 g3 = __ldg(&x[e3.x * 128 + j]);
    __half2 a01 = __float2half2_rn(0.f), a23 = a01;
    a01 = __hfma2(h2b(g0.x), h2b(e0.y), a01); a23 = __hfma2(h2b(g0.y), h2b(e0.y), a23);
    a01 = __hfma2(h2b(g1.x), h2b(e1.y), a01); a23 = __hfma2(h2b(g1.y), h2b(e1.y), a23);
    a01 = __hfma2(h2b(g2.x), h2b(e2.y), a01); a23 = __hfma2(h2b(g2.y), h2b(e2.y), a23);
    a01 = __hfma2(h2b(g3.x), h2b(e3.y), a01); a23 = __hfma2(h2b(g3.y), h2b(e3.y), a23);
    float2 f01 = __half22float2(a01), f23 = __half22float2(a23);
    ax += f01.x; ay += f01.y; az += f23.x; aw += f23.y;
}
__device__ __forceinline__ void gather1(const uint2* __restrict__ x, const int2* se, int i, int j,
                                        float& ax, float& ay, float& az, float& aw) {
    int2 ed = se[i];
    float v = __half2float(__low2half(h2b(ed.y)));
    float4 xv = ldh4(&x[ed.x * 128 + j]);
    ax += v * xv.x; ay += v * xv.y; az += v * xv.z; aw += v * xv.w;
}

// ---------------- fused pre: transpose (blocks < NN) + ELL scatter (rest) ----------------
__global__ __launch_bounds__(512) void k_pre(const float* __restrict__ y,
        const int* __restrict__ r1, const int* __restrict__ c1, const float* __restrict__ v1,
        const int* __restrict__ r2, const int* __restrict__ c2, const float* __restrict__ v2) {
    int t = threadIdx.x;
    if (blockIdx.x < NN) {
        __shared__ float s[512];
        int n = blockIdx.x;
        int b = t >> 4, f = t & 15;
        s[f * 32 + b] = y[b * (NN * 16) + n * 16 + f];
        __syncthreads();
        if (t < 256)
            ((__half2*)g_x0h)[n * 256 + t] = __floats2half2_rn(s[2 * t], s[2 * t + 1]);
    } else {
        int gi = (blockIdx.x - NN) * 512 + t;     // covers [0, 2*NNZT) exactly
        int sup = gi >= NNZT;
        int e = sup ? gi - NNZT : gi;
        const int*   r = sup ? r2 : r1;
        const int*   c = sup ? c2 : c1;
        const float* v = sup ? v2 : v1;
        int row = __ldg(&r[e]);
        int p = atomicAdd(&g_len[sup][row], 1);
        if (p < ELLW) {
            __half2 hv = __half2half2(__float2half_rn(__ldg(&v[e])));
            g_ell[sup][row * ELLW + p] = make_int2(__ldg(&c[e]), (int)*(uint32_t*)&hv);
        }
    }
}

// ---------------- dual-job half SpMM: out = al*(S@hsrc) + be*add ----------------
__global__ __launch_bounds__(128) void k_spmm2(
        int hA, int adfA, int adhA, float alA, float beA, int oA,
        int hB, int adfB, int adhB, float alB, float beB, int oB) {
    __shared__ int2 se[ELLW];
    int unit = blockIdx.x >> 12;
    int n = blockIdx.x & (NN - 1);
    int hid = unit ? hB : hA;
    int adf = unit ? adfB : adfA;
    int adh = unit ? adhB : adhA;
    float al = unit ? alB : alA;
    float be = unit ? beB : beA;
    int oid = unit ? oB : oA;

    int cnt = g_len[unit][n]; if (cnt > ELLW) cnt = ELLW;
    if (threadIdx.x < cnt) se[threadIdx.x] = __ldg(&g_ell[unit][n * ELLW + threadIdx.x]);
    __syncthreads();

    int j = threadIdx.x;
    const uint2* __restrict__ x = (const uint2*)hsel(hid);
    float ax = 0.f, ay = 0.f, az = 0.f, aw = 0.f;
    int i = 0;
    for (; i + 4 <= cnt; i += 4) gather4(x, se, i, j, ax, ay, az, aw);
    for (; i < cnt; ++i)         gather1(x, se, i, j, ax, ay, az, aw);

    float4 r = make_float4(al * ax, al * ay, al * az, al * aw);
    if (adf >= 0) {
        float4 a = __ldg(&((const float4*)fsel(adf))[n * 128 + j]);
        r.x += be * a.x; r.y += be * a.y; r.z += be * a.z; r.w += be * a.w;
    } else if (adh >= 0) {
        float4 a = ldh4(&((const uint2*)hsel(adh))[n * 128 + j]);
        r.x += be * a.x; r.y += be * a.y; r.z += be * a.z; r.w += be * a.w;
    }
    ((uint2*)hsel_w(oid))[n * 128 + j] = f4toh(r);
}

// ---------------- slim HMMA kernel: 4 nodes per block, 256 threads ----------------
#define OFF_A   0
#define OFF_W   21504
#define OFF_C   34944
#define OFF_WO  52352
#define SM_TOT  63232
#define STA 84
#define STW 84
#define STC 68
#define STO 68

__global__ __launch_bounds__(256, 3) void k_mma(const float* __restrict__ Wt,
                                                const float* __restrict__ Wh,
                                                const float* __restrict__ Wo,
                                                const float* __restrict__ blat,
                                                const float* __restrict__ bhid) {
    extern __shared__ __align__(16) char dsm[];
    __half* sA   = (__half*)(dsm + OFF_A);
    __half* sW   = (__half*)(dsm + OFF_W);
    __half* sC   = (__half*)(dsm + OFF_C);
    __half* sWo  = (__half*)(dsm + OFF_WO);

    int tid = threadIdx.x;
    int n0 = blockIdx.x * 4;

    // stage sA: 5 mirrors -> [row][k] (k = f*5+m)
    for (int e = tid; e < 2560; e += 256) {
        int m = e >> 9, idx = e & 511;
        int nd = idx >> 7, j = idx & 127;
        const __half* src = hsel(m);
        uint2 gv = __ldg((const uint2*)&src[(n0 + nd) * 512 + j * 4]);
        __half h[4];
        *(uint2*)h = gv;
        int f = j >> 3, b0 = (j & 7) * 4;
        int k = f * 5 + m;
        int row = nd * 32 + b0;
        sA[(row + 0) * STA + k] = h[0];
        sA[(row + 1) * STA + k] = h[1];
        sA[(row + 2) * STA + k] = h[2];
        sA[(row + 3) * STA + k] = h[3];
    }
    for (int e = tid; e < 6400; e += 256) {
        int o = e % 80, k = e / 80;
        float w = (o < 16) ? Wt[k * 16 + o] : Wh[k * 64 + (o - 16)];
        sW[o * STW + k] = __float2half(w);
    }
    for (int e = tid; e < 5120; e += 256) {
        int p = e % 80, u = e / 80;
        sWo[p * STO + u] = __float2half(Wo[u * 80 + p]);
    }
    __syncthreads();

    int w = tid >> 5, t = tid & 31;
    int g = t >> 2, q = t & 3;
    int rowA = w * 16 + g;
    const __half* aBase = sA + rowA * STA;

    // GEMM1
    {
        float acc[10][4];
#pragma unroll
        for (int nt = 0; nt < 10; nt++)
            for (int p = 0; p < 4; p++) acc[nt][p] = 0.f;
#pragma unroll
        for (int kt = 0; kt < 5; kt++) {
            int k0 = kt * 16 + q * 2;
            uint32_t a0 = *(const uint32_t*)(aBase + k0);
            uint32_t a1 = *(const uint32_t*)(aBase + 8 * STA + k0);
            uint32_t a2 = *(const uint32_t*)(aBase + k0 + 8);
            uint32_t a3 = *(const uint32_t*)(aBase + 8 * STA + k0 + 8);
#pragma unroll
            for (int nt = 0; nt < 10; nt++) {
                const __half* bb = sW + (nt * 8 + g) * STW + k0;
                uint32_t b0 = *(const uint32_t*)bb;
                uint32_t b1 = *(const uint32_t*)(bb + 8);
                mma16816(acc[nt], a0, a1, a2, a3, b0, b1);
            }
        }
#pragma unroll
        for (int nt = 0; nt < 10; nt++) {
            int o = nt * 8 + q * 2;
            if (o < 16) {
                float bl0 = blat[o], bl1 = blat[o + 1];
#pragma unroll
                for (int half = 0; half < 2; half++) {
                    int row = rowA + half * 8;
                    int n = n0 + (row >> 5), b = row & 31;
                    float v0 = acc[nt][half * 2]     + bl0;
                    float v1 = acc[nt][half * 2 + 1] + bl1;
                    g_theta[n * 512 + o * 32 + b]       = 0.5f + 0.5f * tanh_ap(0.5f * v0);
                    g_theta[n * 512 + (o + 1) * 32 + b] = 0.5f + 0.5f * tanh_ap(0.5f * v1);
                }
            } else {
                int u = o - 16;
                float bh0 = bhid[u], bh1 = bhid[u + 1];
#pragma unroll
                for (int half = 0; half < 2; half++) {
                    int row = rowA + half * 8;
                    __half2 hv = __floats2half2_rn(tanh_ap(acc[nt][half * 2] + bh0),
                                                   tanh_ap(acc[nt][half * 2 + 1] + bh1));
                    *(uint32_t*)(sC + row * STC + u) = *(uint32_t*)&hv;
                }
            }
        }
    }
    __syncthreads();

    // GEMM2
    {
        const __half* cBase = sC + rowA * STC;
        float acc[10][4];
#pragma unroll
        for (int nt = 0; nt < 10; nt++)
            for (int p = 0; p < 4; p++) acc[nt][p] = 0.f;
#pragma unroll
        for (int kt = 0; kt < 4; kt++) {
            int k0 = kt * 16 + q * 2;
            uint32_t a0 = *(const uint32_t*)(cBase + k0);
            uint32_t a1 = *(const uint32_t*)(cBase + 8 * STC + k0);
            uint32_t a2 = *(const uint32_t*)(cBase + k0 + 8);
            uint32_t a3 = *(const uint32_t*)(cBase + 8 * STC + k0 + 8);
#pragma unroll
            for (int nt = 0; nt < 10; nt++) {
                const __half* bb = sWo + (nt * 8 + g) * STO + k0;
                uint32_t b0 = *(const uint32_t*)bb;
                uint32_t b1 = *(const uint32_t*)(bb + 8);
                mma16816(acc[nt], a0, a1, a2, a3, b0, b1);
            }
        }
#pragma unroll
        for (int nt = 0; nt < 10; nt++) {
            int p = nt * 8 + q * 2;
            int m = p >> 4, o = p & 15;
            float* zm = g_z[m];
#pragma unroll
            for (int half = 0; half < 2; half++) {
                int row = rowA + half * 8;
                int n = n0 + (row >> 5), b = row & 31;
                float v0 = acc[nt][half * 2], v1 = acc[nt][half * 2 + 1];
                int i0 = n * 512 + o * 32 + b;
                int i1 = n * 512 + (o + 1) * 32 + b;
                zm[i0] = v0; zm[i1] = v1;
                if (m == 2) { g_z2h[i0] = __float2half(v0); g_z2h[i1] = __float2half(v1); }
                else if (m == 4) { g_z4h[i0] = __float2half(v0); g_z4h[i1] = __float2half(v1); }
            }
        }
    }
}

// ---------------- final: S1@p1h + S2@p2h + Z0 - Z2 - Z4 + b -> -theta*tanh ----------------
__global__ __launch_bounds__(128) void k_final(const float* __restrict__ blat, float* __restrict__ out) {
    __shared__ int2 se1[ELLW], se2[ELLW];
    __shared__ float st[512];
    int n = blockIdx.x, j = threadIdx.x;

    int c1n = g_len[0][n]; if (c1n > ELLW) c1n = ELLW;
    int c2n = g_len[1][n]; if (c2n > ELLW) c2n = ELLW;
    if (j < c1n) se1[j] = __ldg(&g_ell[0][n * ELLW + j]);
    else if (j >= 64 && j - 64 < c2n) se2[j - 64] = __ldg(&g_ell[1][n * ELLW + j - 64]);
    __syncthreads();
    // re-zero g_len for next pipeline run (k_pre scatter relies on it)
    if (j < 2) g_len[j][n] = 0;

    const uint2* __restrict__ xp1 = (const uint2*)g_p1h;
    const uint2* __restrict__ xp2 = (const uint2*)g_p2h;
    float ax = 0.f, ay = 0.f, az = 0.f, aw = 0.f;

    int i = 0;
    for (; i + 4 <= c1n; i += 4) gather4(xp1, se1, i, j, ax, ay, az, aw);
    for (; i < c1n; ++i)         gather1(xp1, se1, i, j, ax, ay, az, aw);
    i = 0;
    for (; i + 4 <= c2n; i += 4) gather4(xp2, se2, i, j, ax, ay, az, aw);
    for (; i < c2n; ++i)         gather1(xp2, se2, i, j, ax, ay, az, aw);

    int idx = n * 128 + j;
    float4 t0 = ((const float4*)g_z[0])[idx];
    float4 t2 = ((const float4*)g_z[2])[idx];
    float4 t4 = ((const float4*)g_z[4])[idx];
    float4 tt = ((const float4*)g_theta)[idx];

    int o = j >> 3;
    float bl = blat[o];
    float4 r;
    r.x = -tt.x * tanh_ap(ax + t0.x - t2.x - t4.x + bl);
    r.y = -tt.y * tanh_ap(ay + t0.y - t2.y - t4.y + bl);
    r.z = -tt.z * tanh_ap(az + t0.z - t2.z - t4.z + bl);
    r.w = -tt.w * tanh_ap(aw + t0.w - t2.w - t4.w + bl);
    ((float4*)st)[j] = r;
    __syncthreads();

    int b = j >> 2, qo = j & 3;
    float4 w;
    w.x = st[(qo * 4 + 0) * 32 + b];
    w.y = st[(qo * 4 + 1) * 32 + b];
    w.z = st[(qo * 4 + 2) * 32 + b];
    w.w = st[(qo * 4 + 3) * 32 + b];
    ((float4*)(out + b * (NN * 16) + n * 16))[qo] = w;
}

// ---------------- host launcher ----------------
extern "C" void kernel_launch(void* const* d_in, const int* in_sizes, int n_in,
                              void* d_out, int out_size) {
    (void)in_sizes; (void)n_in; (void)out_size;
    const float* y    = (const float*)d_in[1];
    const float* Wt   = (const float*)d_in[2];
    const float* blat = (const float*)d_in[3];
    const float* Wh   = (const float*)d_in[4];
    const float* bhid = (const float*)d_in[5];
    const float* Wo   = (const float*)d_in[6];
    const int*   r1   = (const int*)d_in[7];
    const int*   c1   = (const int*)d_in[8];
    const float* v1   = (const float*)d_in[9];
    const int*   r2   = (const int*)d_in[10];
    const int*   c2   = (const int*)d_in[11];
    const float* v2   = (const float*)d_in[12];
    float* out = (float*)d_out;

    cudaFuncSetAttribute(k_mma, cudaFuncAttributeMaxDynamicSharedMemorySize, SM_TOT);

    // fused transpose + ELL scatter (g_len zeroed by previous k_final / static init)
    k_pre<<<NN + 2 * NNZT / 512, 512>>>(y, r1, c1, v1, r2, c2, v2);

    // hop1: xs1h = S1@x0h ; xs3h = S2@x0h
    k_spmm2<<<2 * NN, 128>>>(0, -1, -1, 1.f, 0.f, 1,   0, -1, -1, 1.f, 0.f, 3);
    // hop2: xs2h = 2*S1@xs1h - x0h ; xs4h = 2*S2@xs3h - x0h
    k_spmm2<<<2 * NN, 128>>>(1, -1, 0, 2.f, -1.f, 2,   3, -1, 0, 2.f, -1.f, 4);

    // HMMA: theta/c1 GEMM + Z projection   (profiled slot)
    k_mma<<<NN / 4, 256, SM_TOT>>>(Wt, Wh, Wo, blat, bhid);

    // p1h = Z1 + 2*(S1@z2h) ; p2h = Z3 + 2*(S2@z4h)
    k_spmm2<<<2 * NN, 128>>>(5, 0, -1, 2.f, 1.f, 7,   6, 1, -1, 2.f, 1.f, 8);

    // final: second-hop gathers + combine + tanh + gate + transposed store
    k_final<<<NN, 128>>>(blat, out);
}

// round 13
// speedup vs baseline: 1.1903x; 1.1069x over previous
#include <cuda_runtime.h>
#include <cuda_fp16.h>
#include <math.h>
#include <cstdint>

#define NN    4096
#define NNZT  65536
#define ELLW  64

// ---------------- scratch (device globals) ----------------
__device__ int   g_len[2][NN];            // starts 0 (static); k_final re-zeroes
__device__ int2  g_ell[2][NN * ELLW];     // (col, val as duplicated half2)

// fp32 canonical, layout [n][b*16+o]
__device__ float g_zc[NN * 512];          // z0 - z2 - z4
__device__ float g_z1[NN * 512];
__device__ float g_z3[NN * 512];
__device__ float g_theta[NN * 512];

// fp16 mirrors, layout [n][b*16+f]
__device__ __half g_x0h [NN * 512];
__device__ __half g_xs1h[NN * 512];
__device__ __half g_xs2h[NN * 512];
__device__ __half g_xs3h[NN * 512];
__device__ __half g_xs4h[NN * 512];
__device__ __half g_z2h [NN * 512];
__device__ __half g_z4h [NN * 512];
__device__ __half g_p1h [NN * 512];
__device__ __half g_p2h [NN * 512];

__device__ __forceinline__ const __half* hsel(int id) {
    switch (id) {
        case 0: return g_x0h;  case 1: return g_xs1h; case 2: return g_xs2h;
        case 3: return g_xs3h; case 4: return g_xs4h; case 5: return g_z2h;
        case 6: return g_z4h;  case 7: return g_p1h;  default: return g_p2h;
    }
}
__device__ __forceinline__ __half* hsel_w(int id) {
    switch (id) {
        case 1: return g_xs1h; case 2: return g_xs2h; case 3: return g_xs3h;
        case 4: return g_xs4h; case 7: return g_p1h;  default: return g_p2h;
    }
}
__device__ __forceinline__ const float* fsel(int id) {
    return (id == 0) ? g_z1 : g_z3;
}

// ---------------- helpers ----------------
__device__ __forceinline__ __half2 h2b(uint32_t u) { return *(__half2*)&u; }
__device__ __forceinline__ float4 ldh4(const uint2* p) {
    uint2 g = __ldg(p);
    float2 f0 = __half22float2(h2b(g.x)), f1 = __half22float2(h2b(g.y));
    return make_float4(f0.x, f0.y, f1.x, f1.y);
}
__device__ __forceinline__ uint2 f4toh(float4 v) {
    __half2 a = __floats2half2_rn(v.x, v.y);
    __half2 b = __floats2half2_rn(v.z, v.w);
    uint2 r;
    r.x = *(unsigned int*)&a;
    r.y = *(unsigned int*)&b;
    return r;
}
__device__ __forceinline__ float tanh_ap(float x) {
    float r;
    asm("tanh.approx.f32 %0, %1;" : "=f"(r) : "f"(x));
    return r;
}
__device__ __forceinline__ void mma16816(float* c, uint32_t a0, uint32_t a1, uint32_t a2, uint32_t a3,
                                         uint32_t b0, uint32_t b1) {
    asm volatile("mma.sync.aligned.m16n8k16.row.col.f32.f16.f16.f32 "
        "{%0,%1,%2,%3}, {%4,%5,%6,%7}, {%8,%9}, {%0,%1,%2,%3};"
        : "+f"(c[0]), "+f"(c[1]), "+f"(c[2]), "+f"(c[3])
        : "r"(a0), "r"(a1), "r"(a2), "r"(a3), "r"(b0), "r"(b1));
}

__device__ __forceinline__ void gather4(const uint2* __restrict__ x, const int2* se, int i, int j,
                                        float& ax, float& ay, float& az, float& aw) {
    int2 e0 = se[i], e1 = se[i + 1], e2 = se[i + 2], e3 = se[i + 3];
    uint2 g0 = __ldg(&x[e0.x * 128 + j]);
    uint2 g1 = __ldg(&x[e1.x * 128 + j]);
    uint2 g2 = __ldg(&x[e2.x * 128 + j]);
    uint2 g3 = __ldg(&x[e3.x * 128 + j]);
    __half2 a01 = __float2half2_rn(0.f), a23 = a01;
    a01 = __hfma2(h2b(g0.x), h2b(e0.y), a01); a23 = __hfma2(h2b(g0.y), h2b(e0.y), a23);
    a01 = __hfma2(h2b(g1.x), h2b(e1.y), a01); a23 = __hfma2(h2b(g1.y), h2b(e1.y), a23);
    a01 = __hfma2(h2b(g2.x), h2b(e2.y), a01); a23 = __hfma2(h2b(g2.y), h2b(e2.y), a23);
    a01 = __hfma2(h2b(g3.x), h2b(e3.y), a01); a23 = __hfma2(h2b(g3.y), h2b(e3.y), a23);
    float2 f01 = __half22float2(a01), f23 = __half22float2(a23);
    ax += f01.x; ay += f01.y; az += f23.x; aw += f23.y;
}
__device__ __forceinline__ void gather1(const uint2* __restrict__ x, const int2* se, int i, int j,
                                        float& ax, float& ay, float& az, float& aw) {
    int2 ed = se[i];
    float v = __half2float(__low2half(h2b(ed.y)));
    float4 xv = ldh4(&x[ed.x * 128 + j]);
    ax += v * xv.x; ay += v * xv.y; az += v * xv.z; aw += v * xv.w;
}

// ---------------- fused pre: transpose -> x0h [n][b*16+f] (blocks < NN) + ELL scatter ----------------
__global__ __launch_bounds__(512) void k_pre(const float* __restrict__ y,
        const int* __restrict__ r1, const int* __restrict__ c1, const float* __restrict__ v1,
        const int* __restrict__ r2, const int* __restrict__ c2, const float* __restrict__ v2) {
    int t = threadIdx.x;
    if (blockIdx.x < NN) {
        int n = blockIdx.x;
        if (t < 256) {
            int idx2 = t * 2;              // element index b*16+f
            int b = idx2 >> 4, f = idx2 & 15;   // f even
            float2 yv = *(const float2*)&y[b * (NN * 16) + n * 16 + f];
            ((__half2*)g_x0h)[n * 256 + t] = __floats2half2_rn(yv.x, yv.y);
        }
    } else {
        int gi = (blockIdx.x - NN) * 512 + t;     // covers [0, 2*NNZT)
        int sup = gi >= NNZT;
        int e = sup ? gi - NNZT : gi;
        const int*   r = sup ? r2 : r1;
        const int*   c = sup ? c2 : c1;
        const float* v = sup ? v2 : v1;
        int row = __ldg(&r[e]);
        int p = atomicAdd(&g_len[sup][row], 1);
        if (p < ELLW) {
            __half2 hv = __half2half2(__float2half_rn(__ldg(&v[e])));
            g_ell[sup][row * ELLW + p] = make_int2(__ldg(&c[e]), (int)*(uint32_t*)&hv);
        }
    }
}

// ---------------- dual-job half SpMM: out = al*(S@hsrc) + be*add ----------------
__global__ __launch_bounds__(128) void k_spmm2(
        int hA, int adfA, int adhA, float alA, float beA, int oA,
        int hB, int adfB, int adhB, float alB, float beB, int oB) {
    __shared__ int2 se[ELLW];
    int unit = blockIdx.x >> 12;
    int n = blockIdx.x & (NN - 1);
    int hid = unit ? hB : hA;
    int adf = unit ? adfB : adfA;
    int adh = unit ? adhB : adhA;
    float al = unit ? alB : alA;
    float be = unit ? beB : beA;
    int oid = unit ? oB : oA;

    int cnt = g_len[unit][n]; if (cnt > ELLW) cnt = ELLW;
    if (threadIdx.x < cnt) se[threadIdx.x] = __ldg(&g_ell[unit][n * ELLW + threadIdx.x]);
    __syncthreads();

    int j = threadIdx.x;
    const uint2* __restrict__ x = (const uint2*)hsel(hid);
    float ax = 0.f, ay = 0.f, az = 0.f, aw = 0.f;
    int i = 0;
    for (; i + 4 <= cnt; i += 4) gather4(x, se, i, j, ax, ay, az, aw);
    for (; i < cnt; ++i)         gather1(x, se, i, j, ax, ay, az, aw);

    float4 r = make_float4(al * ax, al * ay, al * az, al * aw);
    if (adf >= 0) {
        float4 a = __ldg(&((const float4*)fsel(adf))[n * 128 + j]);
        r.x += be * a.x; r.y += be * a.y; r.z += be * a.z; r.w += be * a.w;
    } else if (adh >= 0) {
        float4 a = ldh4(&((const uint2*)hsel(adh))[n * 128 + j]);
        r.x += be * a.x; r.y += be * a.y; r.z += be * a.z; r.w += be * a.w;
    }
    ((uint2*)hsel_w(oid))[n * 128 + j] = f4toh(r);
}

// ---------------- slim HMMA kernel: 4 nodes per block, 256 threads ----------------
// A layout [row = nd*32+b][k' = m*16+f]; W permuted to k' at stage time.
#define OFF_A   0
#define OFF_W   21504
#define OFF_C   34944
#define OFF_WO  52352
#define SM_TOT  63232
#define STA 84
#define STW 84
#define STC 68
#define STO 68

__global__ __launch_bounds__(256, 3) void k_mma(const float* __restrict__ Wt,
                                                const float* __restrict__ Wh,
                                                const float* __restrict__ Wo,
                                                const float* __restrict__ blat,
                                                const float* __restrict__ bhid) {
    extern __shared__ __align__(16) char dsm[];
    __half* sA   = (__half*)(dsm + OFF_A);
    __half* sW   = (__half*)(dsm + OFF_W);
    __half* sC   = (__half*)(dsm + OFF_C);
    __half* sWo  = (__half*)(dsm + OFF_WO);

    int tid = threadIdx.x;
    int n0 = blockIdx.x * 4;

    // stage sA: 5 mirrors -> [row][k'], each uint2 becomes ONE 8B store
    for (int e = tid; e < 2560; e += 256) {
        int m = e >> 9, idx = e & 511;
        int nd = idx >> 7, j = idx & 127;
        uint2 gv = __ldg(&((const uint2*)hsel(m))[(n0 + nd) * 128 + j]);
        int b = j >> 2, f0 = (j & 3) * 4;
        int row = nd * 32 + b;
        *(uint2*)&sA[row * STA + m * 16 + f0] = gv;
    }
    // stage W^T [o][k'=m*16+f]  (source k = f*5+m)
    for (int e = tid; e < 6400; e += 256) {
        int o = e % 80, kp = e / 80;
        int f = kp & 15, m = kp >> 4;
        int ks = f * 5 + m;
        float w = (o < 16) ? Wt[ks * 16 + o] : Wh[ks * 64 + (o - 16)];
        sW[o * STW + kp] = __float2half(w);
    }
    // stage Wo^T [p][u]
    for (int e = tid; e < 5120; e += 256) {
        int p = e % 80, u = e / 80;
        sWo[p * STO + u] = __float2half(Wo[u * 80 + p]);
    }
    __syncthreads();

    int w = tid >> 5, t = tid & 31;
    int g = t >> 2, q = t & 3;
    int rowA = w * 16 + g;
    const __half* aBase = sA + rowA * STA;

    // GEMM1: C[128x80] = A @ W^T (fp32 accum)
    {
        float acc[10][4];
#pragma unroll
        for (int nt = 0; nt < 10; nt++)
            for (int p = 0; p < 4; p++) acc[nt][p] = 0.f;
#pragma unroll
        for (int kt = 0; kt < 5; kt++) {
            int k0 = kt * 16 + q * 2;
            uint32_t a0 = *(const uint32_t*)(aBase + k0);
            uint32_t a1 = *(const uint32_t*)(aBase + 8 * STA + k0);
            uint32_t a2 = *(const uint32_t*)(aBase + k0 + 8);
            uint32_t a3 = *(const uint32_t*)(aBase + 8 * STA + k0 + 8);
#pragma unroll
            for (int nt = 0; nt < 10; nt++) {
                const __half* bb = sW + (nt * 8 + g) * STW + k0;
                uint32_t b0 = *(const uint32_t*)bb;
                uint32_t b1 = *(const uint32_t*)(bb + 8);
                mma16816(acc[nt], a0, a1, a2, a3, b0, b1);
            }
        }
        // epilogue 1: theta (float2, [n][b*16+o]) + c1 (tanh, half2 into sC)
#pragma unroll
        for (int nt = 0; nt < 10; nt++) {
            int o = nt * 8 + q * 2;
            if (o < 16) {
                float bl0 = blat[o], bl1 = blat[o + 1];
#pragma unroll
                for (int hf = 0; hf < 2; hf++) {
                    int row = rowA + hf * 8;
                    int n = n0 + (row >> 5), b = row & 31;
                    float2 tv;
                    tv.x = 0.5f + 0.5f * tanh_ap(0.5f * (acc[nt][hf * 2]     + bl0));
                    tv.y = 0.5f + 0.5f * tanh_ap(0.5f * (acc[nt][hf * 2 + 1] + bl1));
                    *(float2*)&g_theta[n * 512 + b * 16 + o] = tv;
                }
            } else {
                int u = o - 16;
                float bh0 = bhid[u], bh1 = bhid[u + 1];
#pragma unroll
                for (int hf = 0; hf < 2; hf++) {
                    int row = rowA + hf * 8;
                    __half2 hv = __floats2half2_rn(tanh_ap(acc[nt][hf * 2] + bh0),
                                                   tanh_ap(acc[nt][hf * 2 + 1] + bh1));
                    *(uint32_t*)(sC + row * STC + u) = *(uint32_t*)&hv;
                }
            }
        }
    }
    __syncthreads();

    // GEMM2: Z[128x80] = C1[128x64] @ Wo^T ; epilogue combines zc = z0-z2-z4
    {
        const __half* cBase = sC + rowA * STC;
        float acc[10][4];
#pragma unroll
        for (int nt = 0; nt < 10; nt++)
            for (int p = 0; p < 4; p++) acc[nt][p] = 0.f;
#pragma unroll
        for (int kt = 0; kt < 4; kt++) {
            int k0 = kt * 16 + q * 2;
            uint32_t a0 = *(const uint32_t*)(cBase + k0);
            uint32_t a1 = *(const uint32_t*)(cBase + 8 * STC + k0);
            uint32_t a2 = *(const uint32_t*)(cBase + k0 + 8);
            uint32_t a3 = *(const uint32_t*)(cBase + 8 * STC + k0 + 8);
#pragma unroll
            for (int nt = 0; nt < 10; nt++) {
                const __half* bb = sWo + (nt * 8 + g) * STO + k0;
                uint32_t b0 = *(const uint32_t*)bb;
                uint32_t b1 = *(const uint32_t*)(bb + 8);
                mma16816(acc[nt], a0, a1, a2, a3, b0, b1);
            }
        }
        // nt->(m,o): nt0/1: m0 o={q2, 8+q2}; nt2/3: m1; nt4/5: m2; nt6/7: m3; nt8/9: m4
        int o0 = q * 2, o1 = 8 + q * 2;
#pragma unroll
        for (int hf = 0; hf < 2; hf++) {
            int row = rowA + hf * 8;
            int n = n0 + (row >> 5), b = row & 31;
            int base = n * 512 + b * 16;
            int h2 = hf * 2;
            // zc = z0 - z2 - z4
            float2 zc0, zc1;
            zc0.x = acc[0][h2]     - acc[4][h2]     - acc[8][h2];
            zc0.y = acc[0][h2 + 1] - acc[4][h2 + 1] - acc[8][h2 + 1];
            zc1.x = acc[1][h2]     - acc[5][h2]     - acc[9][h2];
            zc1.y = acc[1][h2 + 1] - acc[5][h2 + 1] - acc[9][h2 + 1];
            *(float2*)&g_zc[base + o0] = zc0;
            *(float2*)&g_zc[base + o1] = zc1;
            // z1, z3 (fp32, spmm add operands)
            *(float2*)&g_z1[base + o0] = make_float2(acc[2][h2], acc[2][h2 + 1]);
            *(float2*)&g_z1[base + o1] = make_float2(acc[3][h2], acc[3][h2 + 1]);
            *(float2*)&g_z3[base + o0] = make_float2(acc[6][h2], acc[6][h2 + 1]);
            *(float2*)&g_z3[base + o1] = make_float2(acc[7][h2], acc[7][h2 + 1]);
            // z2h, z4h mirrors (gather sources)
            __half2 h20 = __floats2half2_rn(acc[4][h2], acc[4][h2 + 1]);
            __half2 h21 = __floats2half2_rn(acc[5][h2], acc[5][h2 + 1]);
            __half2 h40 = __floats2half2_rn(acc[8][h2], acc[8][h2 + 1]);
            __half2 h41 = __floats2half2_rn(acc[9][h2], acc[9][h2 + 1]);
            *(uint32_t*)&g_z2h[base + o0] = *(uint32_t*)&h20;
            *(uint32_t*)&g_z2h[base + o1] = *(uint32_t*)&h21;
            *(uint32_t*)&g_z4h[base + o0] = *(uint32_t*)&h40;
            *(uint32_t*)&g_z4h[base + o1] = *(uint32_t*)&h41;
        }
    }
}

// ---------------- final: S1@p1h + S2@p2h + zc + b -> -theta*tanh, direct store ----------------
__global__ __launch_bounds__(128) void k_final(const float* __restrict__ blat, float* __restrict__ out) {
    __shared__ int2 se1[ELLW], se2[ELLW];
    int n = blockIdx.x, j = threadIdx.x;

    int c1n = g_len[0][n]; if (c1n > ELLW) c1n = ELLW;
    int c2n = g_len[1][n]; if (c2n > ELLW) c2n = ELLW;
    if (j < c1n) se1[j] = __ldg(&g_ell[0][n * ELLW + j]);
    else if (j >= 64 && j - 64 < c2n) se2[j - 64] = __ldg(&g_ell[1][n * ELLW + j - 64]);
    __syncthreads();
    if (j < 2) g_len[j][n] = 0;     // reset for next pipeline run

    const uint2* __restrict__ xp1 = (const uint2*)g_p1h;
    const uint2* __restrict__ xp2 = (const uint2*)g_p2h;
    float ax = 0.f, ay = 0.f, az = 0.f, aw = 0.f;

    int i = 0;
    for (; i + 4 <= c1n; i += 4) gather4(xp1, se1, i, j, ax, ay, az, aw);
    for (; i < c1n; ++i)         gather1(xp1, se1, i, j, ax, ay, az, aw);
    i = 0;
    for (; i + 4 <= c2n; i += 4) gather4(xp2, se2, i, j, ax, ay, az, aw);
    for (; i < c2n; ++i)         gather1(xp2, se2, i, j, ax, ay, az, aw);

    int idx = n * 128 + j;
    float4 tc = ((const float4*)g_zc)[idx];
    float4 tt = ((const float4*)g_theta)[idx];

    int b = j >> 2, o0 = (j & 3) * 4;
    float4 bl = *(const float4*)&blat[o0];

    float4 r;
    r.x = -tt.x * tanh_ap(ax + tc.x + bl.x);
    r.y = -tt.y * tanh_ap(ay + tc.y + bl.y);
    r.z = -tt.z * tanh_ap(az + tc.z + bl.z);
    r.w = -tt.w * tanh_ap(aw + tc.w + bl.w);
    *(float4*)(out + b * (NN * 16) + n * 16 + o0) = r;
}

// ---------------- host launcher ----------------
extern "C" void kernel_launch(void* const* d_in, const int* in_sizes, int n_in,
                              void* d_out, int out_size) {
    (void)in_sizes; (void)n_in; (void)out_size;
    const float* y    = (const float*)d_in[1];
    const float* Wt   = (const float*)d_in[2];
    const float* blat = (const float*)d_in[3];
    const float* Wh   = (const float*)d_in[4];
    const float* bhid = (const float*)d_in[5];
    const float* Wo   = (const float*)d_in[6];
    const int*   r1   = (const int*)d_in[7];
    const int*   c1   = (const int*)d_in[8];
    const float* v1   = (const float*)d_in[9];
    const int*   r2   = (const int*)d_in[10];
    const int*   c2   = (const int*)d_in[11];
    const float* v2   = (const float*)d_in[12];
    float* out = (float*)d_out;

    cudaFuncSetAttribute(k_mma, cudaFuncAttributeMaxDynamicSharedMemorySize, SM_TOT);

    // fused transpose + ELL scatter (g_len zeroed by previous k_final / static init)
    k_pre<<<NN + 2 * NNZT / 512, 512>>>(y, r1, c1, v1, r2, c2, v2);

    // hop1: xs1h = S1@x0h ; xs3h = S2@x0h
    k_spmm2<<<2 * NN, 128>>>(0, -1, -1, 1.f, 0.f, 1,   0, -1, -1, 1.f, 0.f, 3);
    // hop2: xs2h = 2*S1@xs1h - x0h ; xs4h = 2*S2@xs3h - x0h
    k_spmm2<<<2 * NN, 128>>>(1, -1, 0, 2.f, -1.f, 2,   3, -1, 0, 2.f, -1.f, 4);

    // HMMA: theta/c1 GEMM + Z projection + zc combine   (profiled slot)
    k_mma<<<NN / 4, 256, SM_TOT>>>(Wt, Wh, Wo, blat, bhid);

    // p1h = z1 + 2*(S1@z2h) ; p2h = z3 + 2*(S2@z4h)
    k_spmm2<<<2 * NN, 128>>>(5, 0, -1, 2.f, 1.f, 7,   6, 1, -1, 2.f, 1.f, 8);

    // final: second-hop gathers + zc + tanh + gate + direct transposed store
    k_final<<<NN, 128>>>(blat, out);
}

// round 14
// speedup vs baseline: 1.3840x; 1.1628x over previous
#include <cuda_runtime.h>
#include <cuda_fp16.h>
#include <math.h>
#include <cstdint>

#define NN    4096
#define NNZT  65536
#define ELLW  64

// ---------------- scratch (device globals) ----------------
__device__ int   g_len[2][NN];            // starts 0 (static); k_final re-zeroes
__device__ int2  g_ell[2][NN * ELLW];     // (col, val as duplicated half2)

// fp32 canonical, layout [n][b*16+o]
__device__ float g_zc[NN * 512];          // z0 - z2 - z4
__device__ float g_z1[NN * 512];
__device__ float g_z3[NN * 512];
__device__ float g_theta[NN * 512];

// fp16 mirrors, layout [n][b*16+f]
__device__ __half g_x0h [NN * 512];
__device__ __half g_xs1h[NN * 512];
__device__ __half g_xs2h[NN * 512];
__device__ __half g_xs3h[NN * 512];
__device__ __half g_xs4h[NN * 512];
__device__ __half g_z2h [NN * 512];
__device__ __half g_z4h [NN * 512];
__device__ __half g_p1h [NN * 512];
__device__ __half g_p2h [NN * 512];

// pre-converted fp16 weights (padded strides, k' = m*16+f ordering)
__device__ __align__(16) __half g_w16 [80 * 84];   // [o][k'] stride 84
__device__ __align__(16) __half g_wo16[80 * 68];   // [p][u]  stride 68

__device__ __forceinline__ const __half* hsel(int id) {
    switch (id) {
        case 0: return g_x0h;  case 1: return g_xs1h; case 2: return g_xs2h;
        case 3: return g_xs3h; case 4: return g_xs4h; case 5: return g_z2h;
        case 6: return g_z4h;  case 7: return g_p1h;  default: return g_p2h;
    }
}
__device__ __forceinline__ __half* hsel_w(int id) {
    switch (id) {
        case 1: return g_xs1h; case 2: return g_xs2h; case 3: return g_xs3h;
        case 4: return g_xs4h; case 7: return g_p1h;  default: return g_p2h;
    }
}
__device__ __forceinline__ const float* fsel(int id) {
    return (id == 0) ? g_z1 : g_z3;
}

// ---------------- helpers ----------------
__device__ __forceinline__ __half2 h2b(uint32_t u) { return *(__half2*)&u; }
__device__ __forceinline__ float4 ldh4(const uint2* p) {
    uint2 g = __ldg(p);
    float2 f0 = __half22float2(h2b(g.x)), f1 = __half22float2(h2b(g.y));
    return make_float4(f0.x, f0.y, f1.x, f1.y);
}
__device__ __forceinline__ uint2 f4toh(float4 v) {
    __half2 a = __floats2half2_rn(v.x, v.y);
    __half2 b = __floats2half2_rn(v.z, v.w);
    uint2 r;
    r.x = *(unsigned int*)&a;
    r.y = *(unsigned int*)&b;
    return r;
}
__device__ __forceinline__ float tanh_ap(float x) {
    float r;
    asm("tanh.approx.f32 %0, %1;" : "=f"(r) : "f"(x));
    return r;
}
__device__ __forceinline__ void mma16816(float* c, uint32_t a0, uint32_t a1, uint32_t a2, uint32_t a3,
                                         uint32_t b0, uint32_t b1) {
    asm volatile("mma.sync.aligned.m16n8k16.row.col.f32.f16.f16.f32 "
        "{%0,%1,%2,%3}, {%4,%5,%6,%7}, {%8,%9}, {%0,%1,%2,%3};"
        : "+f"(c[0]), "+f"(c[1]), "+f"(c[2]), "+f"(c[3])
        : "r"(a0), "r"(a1), "r"(a2), "r"(a3), "r"(b0), "r"(b1));
}

__device__ __forceinline__ void gather4(const uint2* __restrict__ x, const int2* se, int i, int j,
                                        float& ax, float& ay, float& az, float& aw) {
    int2 e0 = se[i], e1 = se[i + 1], e2 = se[i + 2], e3 = se[i + 3];
    uint2 g0 = __ldg(&x[e0.x * 128 + j]);
    uint2 g1 = __ldg(&x[e1.x * 128 + j]);
    uint2 g2 = __ldg(&x[e2.x * 128 + j]);
    uint2 g3 = __ldg(&x[e3.x * 128 + j]);
    __half2 a01 = __float2half2_rn(0.f), a23 = a01;
    a01 = __hfma2(h2b(g0.x), h2b(e0.y), a01); a23 = __hfma2(h2b(g0.y), h2b(e0.y), a23);
    a01 = __hfma2(h2b(g1.x), h2b(e1.y), a01); a23 = __hfma2(h2b(g1.y), h2b(e1.y), a23);
    a01 = __hfma2(h2b(g2.x), h2b(e2.y), a01); a23 = __hfma2(h2b(g2.y), h2b(e2.y), a23);
    a01 = __hfma2(h2b(g3.x), h2b(e3.y), a01); a23 = __hfma2(h2b(g3.y), h2b(e3.y), a23);
    float2 f01 = __half22float2(a01), f23 = __half22float2(a23);
    ax += f01.x; ay += f01.y; az += f23.x; aw += f23.y;
}
__device__ __forceinline__ void gather1(const uint2* __restrict__ x, const int2* se, int i, int j,
                                        float& ax, float& ay, float& az, float& aw) {
    int2 ed = se[i];
    float v = __half2float(__low2half(h2b(ed.y)));
    float4 xv = ldh4(&x[ed.x * 128 + j]);
    ax += v * xv.x; ay += v * xv.y; az += v * xv.z; aw += v * xv.w;
}

// ---------------- fused pre: transpose | ELL scatter | weight convert ----------------
#define SCAT_BLKS (2 * NNZT / 512)
__global__ __launch_bounds__(512) void k_pre(const float* __restrict__ y,
        const int* __restrict__ r1, const int* __restrict__ c1, const float* __restrict__ v1,
        const int* __restrict__ r2, const int* __restrict__ c2, const float* __restrict__ v2,
        const float* __restrict__ Wt, const float* __restrict__ Wh, const float* __restrict__ Wo) {
    int t = threadIdx.x;
    if (blockIdx.x < NN) {
        int n = blockIdx.x;
        if (t < 256) {
            int idx2 = t * 2;              // element index b*16+f
            int b = idx2 >> 4, f = idx2 & 15;   // f even
            float2 yv = *(const float2*)&y[b * (NN * 16) + n * 16 + f];
            ((__half2*)g_x0h)[n * 256 + t] = __floats2half2_rn(yv.x, yv.y);
        }
    } else if (blockIdx.x < NN + SCAT_BLKS) {
        int gi = (blockIdx.x - NN) * 512 + t;     // covers [0, 2*NNZT)
        int sup = gi >= NNZT;
        int e = sup ? gi - NNZT : gi;
        const int*   r = sup ? r2 : r1;
        const int*   c = sup ? c2 : c1;
        const float* v = sup ? v2 : v1;
        int row = __ldg(&r[e]);
        int p = atomicAdd(&g_len[sup][row], 1);
        if (p < ELLW) {
            __half2 hv = __half2half2(__float2half_rn(__ldg(&v[e])));
            g_ell[sup][row * ELLW + p] = make_int2(__ldg(&c[e]), (int)*(uint32_t*)&hv);
        }
    } else {
        int wi = (blockIdx.x - NN - SCAT_BLKS) * 512 + t;
        if (wi < 6720) {
            int o = wi / 84, kp = wi - o * 84;
            float w = 0.f;
            if (kp < 80) {
                int f = kp & 15, m = kp >> 4;
                int ks = f * 5 + m;
                w = (o < 16) ? Wt[ks * 16 + o] : Wh[ks * 64 + (o - 16)];
            }
            g_w16[wi] = __float2half(w);
        } else if (wi < 6720 + 5440) {
            int wj = wi - 6720;
            int p = wj / 68, u = wj - p * 68;
            g_wo16[wj] = __float2half(u < 64 ? Wo[u * 80 + p] : 0.f);
        }
    }
}

// ---------------- dual-job half SpMM: out = al*(S@hsrc) + be*add ----------------
__global__ __launch_bounds__(128) void k_spmm2(
        int hA, int adfA, int adhA, float alA, float beA, int oA,
        int hB, int adfB, int adhB, float alB, float beB, int oB) {
    __shared__ int2 se[ELLW];
    int unit = blockIdx.x >> 12;
    int n = blockIdx.x & (NN - 1);
    int hid = unit ? hB : hA;
    int adf = unit ? adfB : adfA;
    int adh = unit ? adhB : adhA;
    float al = unit ? alB : alA;
    float be = unit ? beB : beA;
    int oid = unit ? oB : oA;

    int cnt = g_len[unit][n]; if (cnt > ELLW) cnt = ELLW;
    if (threadIdx.x < cnt) se[threadIdx.x] = __ldg(&g_ell[unit][n * ELLW + threadIdx.x]);
    __syncthreads();

    int j = threadIdx.x;
    const uint2* __restrict__ x = (const uint2*)hsel(hid);
    float ax = 0.f, ay = 0.f, az = 0.f, aw = 0.f;
    int i = 0;
    for (; i + 4 <= cnt; i += 4) gather4(x, se, i, j, ax, ay, az, aw);
    for (; i < cnt; ++i)         gather1(x, se, i, j, ax, ay, az, aw);

    float4 r = make_float4(al * ax, al * ay, al * az, al * aw);
    if (adf >= 0) {
        float4 a = __ldg(&((const float4*)fsel(adf))[n * 128 + j]);
        r.x += be * a.x; r.y += be * a.y; r.z += be * a.z; r.w += be * a.w;
    } else if (adh >= 0) {
        float4 a = ldh4(&((const uint2*)hsel(adh))[n * 128 + j]);
        r.x += be * a.x; r.y += be * a.y; r.z += be * a.z; r.w += be * a.w;
    }
    ((uint2*)hsel_w(oid))[n * 128 + j] = f4toh(r);
}

// ---------------- slim HMMA kernel: 4 nodes per block, 256 threads ----------------
// A layout [row = nd*32+b][k' = m*16+f]; weights pre-permuted in g_w16/g_wo16.
#define OFF_A   0
#define OFF_W   21504
#define OFF_C   34944
#define OFF_WO  52352
#define SM_TOT  63232
#define STA 84
#define STW 84
#define STC 68
#define STO 68

__global__ __launch_bounds__(256, 3) void k_mma(const float* __restrict__ blat,
                                                const float* __restrict__ bhid) {
    extern __shared__ __align__(16) char dsm[];
    __half* sA   = (__half*)(dsm + OFF_A);
    __half* sW   = (__half*)(dsm + OFF_W);
    __half* sC   = (__half*)(dsm + OFF_C);
    __half* sWo  = (__half*)(dsm + OFF_WO);

    int tid = threadIdx.x;
    int n0 = blockIdx.x * 4;

    // stage sA: 5 mirrors -> [row][k'], one 8B store per uint2
    for (int e = tid; e < 2560; e += 256) {
        int m = e >> 9, idx = e & 511;
        int nd = idx >> 7, j = idx & 127;
        uint2 gv = __ldg(&((const uint2*)hsel(m))[(n0 + nd) * 128 + j]);
        int b = j >> 2, f0 = (j & 3) * 4;
        int row = nd * 32 + b;
        *(uint2*)&sA[row * STA + m * 16 + f0] = gv;
    }
    // stage weights: flat uint4 memcpy (no div/mod, no convert)
    for (int e = tid; e < 840; e += 256) ((uint4*)sW)[e]  = ((const uint4*)g_w16)[e];
    for (int e = tid; e < 680; e += 256) ((uint4*)sWo)[e] = ((const uint4*)g_wo16)[e];
    __syncthreads();

    int w = tid >> 5, t = tid & 31;
    int g = t >> 2, q = t & 3;
    int rowA = w * 16 + g;
    const __half* aBase = sA + rowA * STA;

    // GEMM1: C[128x80] = A @ W^T (fp32 accum)
    {
        float acc[10][4];
#pragma unroll
        for (int nt = 0; nt < 10; nt++)
            for (int p = 0; p < 4; p++) acc[nt][p] = 0.f;
#pragma unroll
        for (int kt = 0; kt < 5; kt++) {
            int k0 = kt * 16 + q * 2;
            uint32_t a0 = *(const uint32_t*)(aBase + k0);
            uint32_t a1 = *(const uint32_t*)(aBase + 8 * STA + k0);
            uint32_t a2 = *(const uint32_t*)(aBase + k0 + 8);
            uint32_t a3 = *(const uint32_t*)(aBase + 8 * STA + k0 + 8);
#pragma unroll
            for (int nt = 0; nt < 10; nt++) {
                const __half* bb = sW + (nt * 8 + g) * STW + k0;
                uint32_t b0 = *(const uint32_t*)bb;
                uint32_t b1 = *(const uint32_t*)(bb + 8);
                mma16816(acc[nt], a0, a1, a2, a3, b0, b1);
            }
        }
        // epilogue 1: theta (float2, [n][b*16+o]) + c1 (tanh, half2 into sC)
#pragma unroll
        for (int nt = 0; nt < 10; nt++) {
            int o = nt * 8 + q * 2;
            if (o < 16) {
                float bl0 = blat[o], bl1 = blat[o + 1];
#pragma unroll
                for (int hf = 0; hf < 2; hf++) {
                    int row = rowA + hf * 8;
                    int n = n0 + (row >> 5), b = row & 31;
                    float2 tv;
                    tv.x = 0.5f + 0.5f * tanh_ap(0.5f * (acc[nt][hf * 2]     + bl0));
                    tv.y = 0.5f + 0.5f * tanh_ap(0.5f * (acc[nt][hf * 2 + 1] + bl1));
                    *(float2*)&g_theta[n * 512 + b * 16 + o] = tv;
                }
            } else {
                int u = o - 16;
                float bh0 = bhid[u], bh1 = bhid[u + 1];
#pragma unroll
                for (int hf = 0; hf < 2; hf++) {
                    int row = rowA + hf * 8;
                    __half2 hv = __floats2half2_rn(tanh_ap(acc[nt][hf * 2] + bh0),
                                                   tanh_ap(acc[nt][hf * 2 + 1] + bh1));
                    *(uint32_t*)(sC + row * STC + u) = *(uint32_t*)&hv;
                }
            }
        }
    }
    __syncwarp();     // c1 exchange is warp-local (warp w owns sC rows w*16..w*16+15)

    // GEMM2: Z[128x80] = C1[128x64] @ Wo^T ; epilogue combines zc = z0-z2-z4
    {
        const __half* cBase = sC + rowA * STC;
        float acc[10][4];
#pragma unroll
        for (int nt = 0; nt < 10; nt++)
            for (int p = 0; p < 4; p++) acc[nt][p] = 0.f;
#pragma unroll
        for (int kt = 0; kt < 4; kt++) {
            int k0 = kt * 16 + q * 2;
            uint32_t a0 = *(const uint32_t*)(cBase + k0);
            uint32_t a1 = *(const uint32_t*)(cBase + 8 * STC + k0);
            uint32_t a2 = *(const uint32_t*)(cBase + k0 + 8);
            uint32_t a3 = *(const uint32_t*)(cBase + 8 * STC + k0 + 8);
#pragma unroll
            for (int nt = 0; nt < 10; nt++) {
                const __half* bb = sWo + (nt * 8 + g) * STO + k0;
                uint32_t b0 = *(const uint32_t*)bb;
                uint32_t b1 = *(const uint32_t*)(bb + 8);
                mma16816(acc[nt], a0, a1, a2, a3, b0, b1);
            }
        }
        // nt->(m,o): nt0/1: m0 o={q2, 8+q2}; nt2/3: m1; nt4/5: m2; nt6/7: m3; nt8/9: m4
        int o0 = q * 2, o1 = 8 + q * 2;
#pragma unroll
        for (int hf = 0; hf < 2; hf++) {
            int row = rowA + hf * 8;
            int n = n0 + (row >> 5), b = row & 31;
            int base = n * 512 + b * 16;
            int h2 = hf * 2;
            float2 zc0, zc1;
            zc0.x = acc[0][h2]     - acc[4][h2]     - acc[8][h2];
            zc0.y = acc[0][h2 + 1] - acc[4][h2 + 1] - acc[8][h2 + 1];
            zc1.x = acc[1][h2]     - acc[5][h2]     - acc[9][h2];
            zc1.y = acc[1][h2 + 1] - acc[5][h2 + 1] - acc[9][h2 + 1];
            *(float2*)&g_zc[base + o0] = zc0;
            *(float2*)&g_zc[base + o1] = zc1;
            *(float2*)&g_z1[base + o0] = make_float2(acc[2][h2], acc[2][h2 + 1]);
            *(float2*)&g_z1[base + o1] = make_float2(acc[3][h2], acc[3][h2 + 1]);
            *(float2*)&g_z3[base + o0] = make_float2(acc[6][h2], acc[6][h2 + 1]);
            *(float2*)&g_z3[base + o1] = make_float2(acc[7][h2], acc[7][h2 + 1]);
            __half2 h20 = __floats2half2_rn(acc[4][h2], acc[4][h2 + 1]);
            __half2 h21 = __floats2half2_rn(acc[5][h2], acc[5][h2 + 1]);
            __half2 h40 = __floats2half2_rn(acc[8][h2], acc[8][h2 + 1]);
            __half2 h41 = __floats2half2_rn(acc[9][h2], acc[9][h2 + 1]);
            *(uint32_t*)&g_z2h[base + o0] = *(uint32_t*)&h20;
            *(uint32_t*)&g_z2h[base + o1] = *(uint32_t*)&h21;
            *(uint32_t*)&g_z4h[base + o0] = *(uint32_t*)&h40;
            *(uint32_t*)&g_z4h[base + o1] = *(uint32_t*)&h41;
        }
    }
}

// ---------------- final: S1@p1h + S2@p2h + zc + b -> -theta*tanh, direct store ----------------
__global__ __launch_bounds__(128) void k_final(const float* __restrict__ blat, float* __restrict__ out) {
    __shared__ int2 se1[ELLW], se2[ELLW];
    int n = blockIdx.x, j = threadIdx.x;

    int c1n = g_len[0][n]; if (c1n > ELLW) c1n = ELLW;
    int c2n = g_len[1][n]; if (c2n > ELLW) c2n = ELLW;
    if (j < c1n) se1[j] = __ldg(&g_ell[0][n * ELLW + j]);
    else if (j >= 64 && j - 64 < c2n) se2[j - 64] = __ldg(&g_ell[1][n * ELLW + j - 64]);
    __syncthreads();
    if (j < 2) g_len[j][n] = 0;     // reset for next pipeline run

    const uint2* __restrict__ xp1 = (const uint2*)g_p1h;
    const uint2* __restrict__ xp2 = (const uint2*)g_p2h;
    float ax = 0.f, ay = 0.f, az = 0.f, aw = 0.f;

    int i = 0;
    for (; i + 4 <= c1n; i += 4) gather4(xp1, se1, i, j, ax, ay, az, aw);
    for (; i < c1n; ++i)         gather1(xp1, se1, i, j, ax, ay, az, aw);
    i = 0;
    for (; i + 4 <= c2n; i += 4) gather4(xp2, se2, i, j, ax, ay, az, aw);
    for (; i < c2n; ++i)         gather1(xp2, se2, i, j, ax, ay, az, aw);

    int idx = n * 128 + j;
    float4 tc = ((const float4*)g_zc)[idx];
    float4 tt = ((const float4*)g_theta)[idx];

    int b = j >> 2, o0 = (j & 3) * 4;
    float4 bl = *(const float4*)&blat[o0];

    float4 r;
    r.x = -tt.x * tanh_ap(ax + tc.x + bl.x);
    r.y = -tt.y * tanh_ap(ay + tc.y + bl.y);
    r.z = -tt.z * tanh_ap(az + tc.z + bl.z);
    r.w = -tt.w * tanh_ap(aw + tc.w + bl.w);
    *(float4*)(out + b * (NN * 16) + n * 16 + o0) = r;
}

// ---------------- host launcher ----------------
extern "C" void kernel_launch(void* const* d_in, const int* in_sizes, int n_in,
                              void* d_out, int out_size) {
    (void)in_sizes; (void)n_in; (void)out_size;
    const float* y    = (const float*)d_in[1];
    const float* Wt   = (const float*)d_in[2];
    const float* blat = (const float*)d_in[3];
    const float* Wh   = (const float*)d_in[4];
    const float* bhid = (const float*)d_in[5];
    const float* Wo   = (const float*)d_in[6];
    const int*   r1   = (const int*)d_in[7];
    const int*   c1   = (const int*)d_in[8];
    const float* v1   = (const float*)d_in[9];
    const int*   r2   = (const int*)d_in[10];
    const int*   c2   = (const int*)d_in[11];
    const float* v2   = (const float*)d_in[12];
    float* out = (float*)d_out;

    cudaFuncSetAttribute(k_mma, cudaFuncAttributeMaxDynamicSharedMemorySize, SM_TOT);

    // fused transpose + ELL scatter + weight convert
    k_pre<<<NN + SCAT_BLKS + 24, 512>>>(y, r1, c1, v1, r2, c2, v2, Wt, Wh, Wo);

    // hop1: xs1h = S1@x0h ; xs3h = S2@x0h
    k_spmm2<<<2 * NN, 128>>>(0, -1, -1, 1.f, 0.f, 1,   0, -1, -1, 1.f, 0.f, 3);
    // hop2: xs2h = 2*S1@xs1h - x0h ; xs4h = 2*S2@xs3h - x0h
    k_spmm2<<<2 * NN, 128>>>(1, -1, 0, 2.f, -1.f, 2,   3, -1, 0, 2.f, -1.f, 4);

    // HMMA: theta/c1 GEMM + Z projection + zc combine   (profiled slot)
    k_mma<<<NN / 4, 256, SM_TOT>>>(blat, bhid);

    // p1h = z1 + 2*(S1@z2h) ; p2h = z3 + 2*(S2@z4h)
    k_spmm2<<<2 * NN, 128>>>(5, 0, -1, 2.f, 1.f, 7,   6, 1, -1, 2.f, 1.f, 8);

    // final: second-hop gathers + zc + tanh + gate + direct transposed store
    k_final<<<NN, 128>>>(blat, out);
}

// round 15
// speedup vs baseline: 1.4715x; 1.0632x over previous
#include <cuda_runtime.h>
#include <cuda_fp16.h>
#include <math.h>
#include <cstdint>

#define NN    4096
#define NNZT  65536
#define ELLW  64

// ---------------- scratch (device globals) ----------------
__device__ int   g_len[2][NN];            // starts 0 (static); k_final re-zeroes
__device__ __align__(16) int2 g_ell[2][NN * ELLW];   // (col, val as duplicated half2)

// fp32 canonical, layout [n][b*16+o]
__device__ __align__(16) float g_zc[NN * 512];       // z0 - z2 - z4
__device__ __align__(16) float g_z1[NN * 512];
__device__ __align__(16) float g_z3[NN * 512];
__device__ __align__(16) float g_theta[NN * 512];

// fp16 mirrors, layout [n][b*16+f]
__device__ __align__(16) __half g_x0h [NN * 512];
__device__ __align__(16) __half g_xs1h[NN * 512];
__device__ __align__(16) __half g_xs2h[NN * 512];
__device__ __align__(16) __half g_xs3h[NN * 512];
__device__ __align__(16) __half g_xs4h[NN * 512];
__device__ __align__(16) __half g_z2h [NN * 512];
__device__ __align__(16) __half g_z4h [NN * 512];
__device__ __align__(16) __half g_p1h [NN * 512];
__device__ __align__(16) __half g_p2h [NN * 512];

// pre-converted fp16 weights (padded strides, k' = m*16+f ordering)
__device__ __align__(16) __half g_w16 [80 * 84];   // [o][k'] stride 84
__device__ __align__(16) __half g_wo16[80 * 68];   // [p][u]  stride 68

__device__ __forceinline__ const __half* hsel(int id) {
    switch (id) {
        case 0: return g_x0h;  case 1: return g_xs1h; case 2: return g_xs2h;
        case 3: return g_xs3h; case 4: return g_xs4h; case 5: return g_z2h;
        case 6: return g_z4h;  case 7: return g_p1h;  default: return g_p2h;
    }
}
__device__ __forceinline__ __half* hsel_w(int id) {
    switch (id) {
        case 1: return g_xs1h; case 2: return g_xs2h; case 3: return g_xs3h;
        case 4: return g_xs4h; case 7: return g_p1h;  default: return g_p2h;
    }
}
__device__ __forceinline__ const float* fsel(int id) {
    return (id == 0) ? g_z1 : g_z3;
}

// ---------------- helpers ----------------
__device__ __forceinline__ __half2 h2b(uint32_t u) { return *(__half2*)&u; }
__device__ __forceinline__ float tanh_ap(float x) {
    float r;
    asm("tanh.approx.f32 %0, %1;" : "=f"(r) : "f"(x));
    return r;
}
__device__ __forceinline__ uint32_t packh2(float a, float b) {
    __half2 h = __floats2half2_rn(a, b);
    return *(uint32_t*)&h;
}
__device__ __forceinline__ void mma16816(float* c, uint32_t a0, uint32_t a1, uint32_t a2, uint32_t a3,
                                         uint32_t b0, uint32_t b1) {
    asm volatile("mma.sync.aligned.m16n8k16.row.col.f32.f16.f16.f32 "
        "{%0,%1,%2,%3}, {%4,%5,%6,%7}, {%8,%9}, {%0,%1,%2,%3};"
        : "+f"(c[0]), "+f"(c[1]), "+f"(c[2]), "+f"(c[3])
        : "r"(a0), "r"(a1), "r"(a2), "r"(a3), "r"(b0), "r"(b1));
}

// wide 4-edge gather: 8 elements per thread (uint4), fp16 inner accum, fp32 flush
__device__ __forceinline__ void gather4w(const uint4* __restrict__ x, const int2* se, int i, int j,
                                         float* acc) {
    int2 e0 = se[i], e1 = se[i + 1], e2 = se[i + 2], e3 = se[i + 3];
    uint4 g0 = __ldg(&x[e0.x * 64 + j]);
    uint4 g1 = __ldg(&x[e1.x * 64 + j]);
    uint4 g2 = __ldg(&x[e2.x * 64 + j]);
    uint4 g3 = __ldg(&x[e3.x * 64 + j]);
    __half2 z = __float2half2_rn(0.f);
    __half2 a0 = z, a1 = z, a2 = z, a3 = z;
    __half2 w0 = h2b(e0.y), w1 = h2b(e1.y), w2 = h2b(e2.y), w3 = h2b(e3.y);
    a0 = __hfma2(h2b(g0.x), w0, a0); a1 = __hfma2(h2b(g0.y), w0, a1);
    a2 = __hfma2(h2b(g0.z), w0, a2); a3 = __hfma2(h2b(g0.w), w0, a3);
    a0 = __hfma2(h2b(g1.x), w1, a0); a1 = __hfma2(h2b(g1.y), w1, a1);
    a2 = __hfma2(h2b(g1.z), w1, a2); a3 = __hfma2(h2b(g1.w), w1, a3);
    a0 = __hfma2(h2b(g2.x), w2, a0); a1 = __hfma2(h2b(g2.y), w2, a1);
    a2 = __hfma2(h2b(g2.z), w2, a2); a3 = __hfma2(h2b(g2.w), w2, a3);
    a0 = __hfma2(h2b(g3.x), w3, a0); a1 = __hfma2(h2b(g3.y), w3, a1);
    a2 = __hfma2(h2b(g3.z), w3, a2); a3 = __hfma2(h2b(g3.w), w3, a3);
    float2 f0 = __half22float2(a0), f1 = __half22float2(a1);
    float2 f2 = __half22float2(a2), f3 = __half22float2(a3);
    acc[0] += f0.x; acc[1] += f0.y; acc[2] += f1.x; acc[3] += f1.y;
    acc[4] += f2.x; acc[5] += f2.y; acc[6] += f3.x; acc[7] += f3.y;
}
__device__ __forceinline__ void gather1w(const uint4* __restrict__ x, const int2* se, int i, int j,
                                         float* acc) {
    int2 ed = se[i];
    float v = __half2float(__low2half(h2b(ed.y)));
    uint4 g = __ldg(&x[ed.x * 64 + j]);
    float2 f0 = __half22float2(h2b(g.x)), f1 = __half22float2(h2b(g.y));
    float2 f2 = __half22float2(h2b(g.z)), f3 = __half22float2(h2b(g.w));
    acc[0] += v * f0.x; acc[1] += v * f0.y; acc[2] += v * f1.x; acc[3] += v * f1.y;
    acc[4] += v * f2.x; acc[5] += v * f2.y; acc[6] += v * f3.x; acc[7] += v * f3.y;
}

// ---------------- fused pre: transpose | ELL scatter | weight convert ----------------
#define SCAT_BLKS (2 * NNZT / 512)
__global__ __launch_bounds__(512) void k_pre(const float* __restrict__ y,
        const int* __restrict__ r1, const int* __restrict__ c1, const float* __restrict__ v1,
        const int* __restrict__ r2, const int* __restrict__ c2, const float* __restrict__ v2,
        const float* __restrict__ Wt, const float* __restrict__ Wh, const float* __restrict__ Wo) {
    int t = threadIdx.x;
    if (blockIdx.x < NN) {
        int n = blockIdx.x;
        if (t < 256) {
            int idx2 = t * 2;              // element index b*16+f
            int b = idx2 >> 4, f = idx2 & 15;
            float2 yv = *(const float2*)&y[b * (NN * 16) + n * 16 + f];
            ((__half2*)g_x0h)[n * 256 + t] = __floats2half2_rn(yv.x, yv.y);
        }
    } else if (blockIdx.x < NN + SCAT_BLKS) {
        int gi = (blockIdx.x - NN) * 512 + t;     // covers [0, 2*NNZT)
        int sup = gi >= NNZT;
        int e = sup ? gi - NNZT : gi;
        const int*   r = sup ? r2 : r1;
        const int*   c = sup ? c2 : c1;
        const float* v = sup ? v2 : v1;
        int row = __ldg(&r[e]);
        int p = atomicAdd(&g_len[sup][row], 1);
        if (p < ELLW) {
            __half2 hv = __half2half2(__float2half_rn(__ldg(&v[e])));
            g_ell[sup][row * ELLW + p] = make_int2(__ldg(&c[e]), (int)*(uint32_t*)&hv);
        }
    } else {
        int wi = (blockIdx.x - NN - SCAT_BLKS) * 512 + t;
        if (wi < 6720) {
            int o = wi / 84, kp = wi - o * 84;
            float w = 0.f;
            if (kp < 80) {
                int f = kp & 15, m = kp >> 4;
                int ks = f * 5 + m;
                w = (o < 16) ? Wt[ks * 16 + o] : Wh[ks * 64 + (o - 16)];
            }
            g_w16[wi] = __float2half(w);
        } else if (wi < 6720 + 5440) {
            int wj = wi - 6720;
            int p = wj / 68, u = wj - p * 68;
            g_wo16[wj] = __float2half(u < 64 ? Wo[u * 80 + p] : 0.f);
        }
    }
}

// ---------------- dual-job wide half SpMM: out = al*(S@hsrc) + be*add ----------------
// grid 8192 (unit = job), block 64 (each thread = one uint4 of the row)
__global__ __launch_bounds__(64) void k_spmm2(
        int hA, int adfA, int adhA, float alA, float beA, int oA,
        int hB, int adfB, int adhB, float alB, float beB, int oB) {
    __shared__ int2 se[ELLW];
    int unit = blockIdx.x >> 12;
    int n = blockIdx.x & (NN - 1);
    int hid = unit ? hB : hA;
    int adf = unit ? adfB : adfA;
    int adh = unit ? adhB : adhA;
    float al = unit ? alB : alA;
    float be = unit ? beB : beA;
    int oid = unit ? oB : oA;

    int cnt = g_len[unit][n]; if (cnt > ELLW) cnt = ELLW;
    if (threadIdx.x < cnt) se[threadIdx.x] = __ldg(&g_ell[unit][n * ELLW + threadIdx.x]);
    __syncthreads();

    int j = threadIdx.x;
    const uint4* __restrict__ x = (const uint4*)hsel(hid);
    float acc[8] = {0.f, 0.f, 0.f, 0.f, 0.f, 0.f, 0.f, 0.f};
    int i = 0;
    for (; i + 4 <= cnt; i += 4) gather4w(x, se, i, j, acc);
    for (; i < cnt; ++i)         gather1w(x, se, i, j, acc);

#pragma unroll
    for (int p = 0; p < 8; p++) acc[p] *= al;
    if (adf >= 0) {
        const float4* ad = (const float4*)fsel(adf);
        float4 a0 = __ldg(&ad[n * 128 + j * 2]);
        float4 a1 = __ldg(&ad[n * 128 + j * 2 + 1]);
        acc[0] += be * a0.x; acc[1] += be * a0.y; acc[2] += be * a0.z; acc[3] += be * a0.w;
        acc[4] += be * a1.x; acc[5] += be * a1.y; acc[6] += be * a1.z; acc[7] += be * a1.w;
    } else if (adh >= 0) {
        uint4 av = __ldg(&((const uint4*)hsel(adh))[n * 64 + j]);
        float2 f0 = __half22float2(h2b(av.x)), f1 = __half22float2(h2b(av.y));
        float2 f2 = __half22float2(h2b(av.z)), f3 = __half22float2(h2b(av.w));
        acc[0] += be * f0.x; acc[1] += be * f0.y; acc[2] += be * f1.x; acc[3] += be * f1.y;
        acc[4] += be * f2.x; acc[5] += be * f2.y; acc[6] += be * f3.x; acc[7] += be * f3.y;
    }
    uint4 o;
    o.x = packh2(acc[0], acc[1]); o.y = packh2(acc[2], acc[3]);
    o.z = packh2(acc[4], acc[5]); o.w = packh2(acc[6], acc[7]);
    ((uint4*)hsel_w(oid))[n * 64 + j] = o;
}

// ---------------- slim HMMA kernel: 4 nodes per block, 256 threads ----------------
// A layout [row = nd*32+b][k' = m*16+f] stride 88 (16B-aligned rows for uint4 staging)
#define OFF_A   0
#define OFF_W   22528
#define OFF_C   35968
#define OFF_WO  53376
#define SM_TOT  64256
#define STA 88
#define STW 84
#define STC 68
#define STO 68

__global__ __launch_bounds__(256, 3) void k_mma(const float* __restrict__ blat,
                                                const float* __restrict__ bhid) {
    extern __shared__ __align__(16) char dsm[];
    __half* sA   = (__half*)(dsm + OFF_A);
    __half* sW   = (__half*)(dsm + OFF_W);
    __half* sC   = (__half*)(dsm + OFF_C);
    __half* sWo  = (__half*)(dsm + OFF_WO);

    int tid = threadIdx.x;
    int n0 = blockIdx.x * 4;

    // stage sA: 5 mirrors -> [row][k'], one LDG.128 + one aligned STS.128 per unit
    for (int e = tid; e < 1280; e += 256) {
        int m = e >> 8, idx = e & 255;
        int nd = idx >> 6, j = idx & 63;
        uint4 gv = __ldg(&((const uint4*)hsel(m))[(n0 + nd) * 64 + j]);
        int b = j >> 1, f0 = (j & 1) * 8;
        int row = nd * 32 + b;
        *(uint4*)&sA[row * STA + m * 16 + f0] = gv;
    }
    // stage weights: flat uint4 memcpy
    for (int e = tid; e < 840; e += 256) ((uint4*)sW)[e]  = ((const uint4*)g_w16)[e];
    for (int e = tid; e < 680; e += 256) ((uint4*)sWo)[e] = ((const uint4*)g_wo16)[e];
    __syncthreads();

    int w = tid >> 5, t = tid & 31;
    int g = t >> 2, q = t & 3;
    int rowA = w * 16 + g;
    const __half* aBase = sA + rowA * STA;

    // GEMM1: C[128x80] = A @ W^T (fp32 accum)
    {
        float acc[10][4];
#pragma unroll
        for (int nt = 0; nt < 10; nt++)
            for (int p = 0; p < 4; p++) acc[nt][p] = 0.f;
#pragma unroll
        for (int kt = 0; kt < 5; kt++) {
            int k0 = kt * 16 + q * 2;
            uint32_t a0 = *(const uint32_t*)(aBase + k0);
            uint32_t a1 = *(const uint32_t*)(aBase + 8 * STA + k0);
            uint32_t a2 = *(const uint32_t*)(aBase + k0 + 8);
            uint32_t a3 = *(const uint32_t*)(aBase + 8 * STA + k0 + 8);
#pragma unroll
            for (int nt = 0; nt < 10; nt++) {
                const __half* bb = sW + (nt * 8 + g) * STW + k0;
                uint32_t b0 = *(const uint32_t*)bb;
                uint32_t b1 = *(const uint32_t*)(bb + 8);
                mma16816(acc[nt], a0, a1, a2, a3, b0, b1);
            }
        }
        // epilogue 1: theta (float2, [n][b*16+o]) + c1 (tanh, half2 into sC)
#pragma unroll
        for (int nt = 0; nt < 10; nt++) {
            int o = nt * 8 + q * 2;
            if (o < 16) {
                float bl0 = blat[o], bl1 = blat[o + 1];
#pragma unroll
                for (int hf = 0; hf < 2; hf++) {
                    int row = rowA + hf * 8;
                    int n = n0 + (row >> 5), b = row & 31;
                    float2 tv;
                    tv.x = 0.5f + 0.5f * tanh_ap(0.5f * (acc[nt][hf * 2]     + bl0));
                    tv.y = 0.5f + 0.5f * tanh_ap(0.5f * (acc[nt][hf * 2 + 1] + bl1));
                    *(float2*)&g_theta[n * 512 + b * 16 + o] = tv;
                }
            } else {
                int u = o - 16;
                float bh0 = bhid[u], bh1 = bhid[u + 1];
#pragma unroll
                for (int hf = 0; hf < 2; hf++) {
                    int row = rowA + hf * 8;
                    *(uint32_t*)(sC + row * STC + u) =
                        packh2(tanh_ap(acc[nt][hf * 2] + bh0), tanh_ap(acc[nt][hf * 2 + 1] + bh1));
                }
            }
        }
    }
    __syncwarp();     // c1 exchange is warp-local (warp w owns sC rows w*16..w*16+15)

    // GEMM2: Z[128x80] = C1[128x64] @ Wo^T ; epilogue combines zc = z0-z2-z4
    {
        const __half* cBase = sC + rowA * STC;
        float acc[10][4];
#pragma unroll
        for (int nt = 0; nt < 10; nt++)
            for (int p = 0; p < 4; p++) acc[nt][p] = 0.f;
#pragma unroll
        for (int kt = 0; kt < 4; kt++) {
            int k0 = kt * 16 + q * 2;
            uint32_t a0 = *(const uint32_t*)(cBase + k0);
            uint32_t a1 = *(const uint32_t*)(cBase + 8 * STC + k0);
            uint32_t a2 = *(const uint32_t*)(cBase + k0 + 8);
            uint32_t a3 = *(const uint32_t*)(cBase + 8 * STC + k0 + 8);
#pragma unroll
            for (int nt = 0; nt < 10; nt++) {
                const __half* bb = sWo + (nt * 8 + g) * STO + k0;
                uint32_t b0 = *(const uint32_t*)bb;
                uint32_t b1 = *(const uint32_t*)(bb + 8);
                mma16816(acc[nt], a0, a1, a2, a3, b0, b1);
            }
        }
        // nt->(m,o): nt0/1: m0 o={q2, 8+q2}; nt2/3: m1; nt4/5: m2; nt6/7: m3; nt8/9: m4
        int o0 = q * 2, o1 = 8 + q * 2;
#pragma unroll
        for (int hf = 0; hf < 2; hf++) {
            int row = rowA + hf * 8;
            int n = n0 + (row >> 5), b = row & 31;
            int base = n * 512 + b * 16;
            int h2 = hf * 2;
            float2 zc0, zc1;
            zc0.x = acc[0][h2]     - acc[4][h2]     - acc[8][h2];
            zc0.y = acc[0][h2 + 1] - acc[4][h2 + 1] - acc[8][h2 + 1];
            zc1.x = acc[1][h2]     - acc[5][h2]     - acc[9][h2];
            zc1.y = acc[1][h2 + 1] - acc[5][h2 + 1] - acc[9][h2 + 1];
            *(float2*)&g_zc[base + o0] = zc0;
            *(float2*)&g_zc[base + o1] = zc1;
            *(float2*)&g_z1[base + o0] = make_float2(acc[2][h2], acc[2][h2 + 1]);
            *(float2*)&g_z1[base + o1] = make_float2(acc[3][h2], acc[3][h2 + 1]);
            *(float2*)&g_z3[base + o0] = make_float2(acc[6][h2], acc[6][h2 + 1]);
            *(float2*)&g_z3[base + o1] = make_float2(acc[7][h2], acc[7][h2 + 1]);
            *(uint32_t*)&g_z2h[base + o0] = packh2(acc[4][h2], acc[4][h2 + 1]);
            *(uint32_t*)&g_z2h[base + o1] = packh2(acc[5][h2], acc[5][h2 + 1]);
            *(uint32_t*)&g_z4h[base + o0] = packh2(acc[8][h2], acc[8][h2 + 1]);
            *(uint32_t*)&g_z4h[base + o1] = packh2(acc[9][h2], acc[9][h2 + 1]);
        }
    }
}

// ---------------- final: S1@p1h + S2@p2h + zc + b -> -theta*tanh, direct store ----------------
__global__ __launch_bounds__(64) void k_final(const float* __restrict__ blat, float* __restrict__ out) {
    __shared__ int2 se1[ELLW], se2[ELLW];
    int n = blockIdx.x, j = threadIdx.x;

    int c1n = g_len[0][n]; if (c1n > ELLW) c1n = ELLW;
    int c2n = g_len[1][n]; if (c2n > ELLW) c2n = ELLW;
    if (j < c1n) se1[j] = __ldg(&g_ell[0][n * ELLW + j]);
    if (j < c2n) se2[j] = __ldg(&g_ell[1][n * ELLW + j]);
    __syncthreads();
    if (j < 2) g_len[j][n] = 0;     // reset for next pipeline run

    const uint4* __restrict__ xp1 = (const uint4*)g_p1h;
    const uint4* __restrict__ xp2 = (const uint4*)g_p2h;
    float acc[8] = {0.f, 0.f, 0.f, 0.f, 0.f, 0.f, 0.f, 0.f};

    int i = 0;
    for (; i + 4 <= c1n; i += 4) gather4w(xp1, se1, i, j, acc);
    for (; i < c1n; ++i)         gather1w(xp1, se1, i, j, acc);
    i = 0;
    for (; i + 4 <= c2n; i += 4) gather4w(xp2, se2, i, j, acc);
    for (; i < c2n; ++i)         gather1w(xp2, se2, i, j, acc);

    int idx = n * 128 + j * 2;
    float4 tc0 = ((const float4*)g_zc)[idx];
    float4 tc1 = ((const float4*)g_zc)[idx + 1];
    float4 tt0 = ((const float4*)g_theta)[idx];
    float4 tt1 = ((const float4*)g_theta)[idx + 1];

    int b = j >> 1, o0 = (j & 1) * 8;
    float4 bl0 = *(const float4*)&blat[o0];
    float4 bl1 = *(const float4*)&blat[o0 + 4];

    float4 r0, r1;
    r0.x = -tt0.x * tanh_ap(acc[0] + tc0.x + bl0.x);
    r0.y = -tt0.y * tanh_ap(acc[1] + tc0.y + bl0.y);
    r0.z = -tt0.z * tanh_ap(acc[2] + tc0.z + bl0.z);
    r0.w = -tt0.w * tanh_ap(acc[3] + tc0.w + bl0.w);
    r1.x = -tt1.x * tanh_ap(acc[4] + tc1.x + bl1.x);
    r1.y = -tt1.y * tanh_ap(acc[5] + tc1.y + bl1.y);
    r1.z = -tt1.z * tanh_ap(acc[6] + tc1.z + bl1.z);
    r1.w = -tt1.w * tanh_ap(acc[7] + tc1.w + bl1.w);
    float* dst = out + b * (NN * 16) + n * 16 + o0;
    *(float4*)dst = r0;
    *(float4*)(dst + 4) = r1;
}

// ---------------- host launcher ----------------
extern "C" void kernel_launch(void* const* d_in, const int* in_sizes, int n_in,
                              void* d_out, int out_size) {
    (void)in_sizes; (void)n_in; (void)out_size;
    const float* y    = (const float*)d_in[1];
    const float* Wt   = (const float*)d_in[2];
    const float* blat = (const float*)d_in[3];
    const float* Wh   = (const float*)d_in[4];
    const float* bhid = (const float*)d_in[5];
    const float* Wo   = (const float*)d_in[6];
    const int*   r1   = (const int*)d_in[7];
    const int*   c1   = (const int*)d_in[8];
    const float* v1   = (const float*)d_in[9];
    const int*   r2   = (const int*)d_in[10];
    const int*   c2   = (const int*)d_in[11];
    const float* v2   = (const float*)d_in[12];
    float* out = (float*)d_out;

    cudaFuncSetAttribute(k_mma, cudaFuncAttributeMaxDynamicSharedMemorySize, SM_TOT);

    // fused transpose + ELL scatter + weight convert
    k_pre<<<NN + SCAT_BLKS + 24, 512>>>(y, r1, c1, v1, r2, c2, v2, Wt, Wh, Wo);

    // hop1: xs1h = S1@x0h ; xs3h = S2@x0h
    k_spmm2<<<2 * NN, 64>>>(0, -1, -1, 1.f, 0.f, 1,   0, -1, -1, 1.f, 0.f, 3);
    // hop2: xs2h = 2*S1@xs1h - x0h ; xs4h = 2*S2@xs3h - x0h
    k_spmm2<<<2 * NN, 64>>>(1, -1, 0, 2.f, -1.f, 2,   3, -1, 0, 2.f, -1.f, 4);

    // HMMA: theta/c1 GEMM + Z projection + zc combine   (profiled slot)
    k_mma<<<NN / 4, 256, SM_TOT>>>(blat, bhid);

    // p1h = z1 + 2*(S1@z2h) ; p2h = z3 + 2*(S2@z4h)
    k_spmm2<<<2 * NN, 64>>>(5, 0, -1, 2.f, 1.f, 7,   6, 1, -1, 2.f, 1.f, 8);

    // final: second-hop gathers + zc + tanh + gate + direct transposed store
    k_final<<<NN, 64>>>(blat, out);
}

// round 16
// speedup vs baseline: 1.5083x; 1.0250x over previous
#include <cuda_runtime.h>
#include <cuda_fp16.h>
#include <math.h>
#include <cstdint>

#define NN    4096
#define NNZT  65536
#define ELLW  64

// ---------------- scratch (device globals) ----------------
__device__ int   g_len[2][NN];            // starts 0 (static); k_final re-zeroes
__device__ __align__(16) int2 g_ell[2][NN * ELLW];   // (col, val as duplicated half2)

// fp32 canonical, layout [n][b*16+o]
__device__ __align__(16) float g_zc[NN * 512];       // z0 - z2 - z4
__device__ __align__(16) float g_z1[NN * 512];
__device__ __align__(16) float g_z3[NN * 512];
__device__ __align__(16) float g_theta[NN * 512];

// fp16 mirrors, layout [n][b*16+f]
__device__ __align__(16) __half g_x0h [NN * 512];
__device__ __align__(16) __half g_xs1h[NN * 512];
__device__ __align__(16) __half g_xs2h[NN * 512];
__device__ __align__(16) __half g_xs3h[NN * 512];
__device__ __align__(16) __half g_xs4h[NN * 512];
__device__ __align__(16) __half g_z2h [NN * 512];
__device__ __align__(16) __half g_z4h [NN * 512];
__device__ __align__(16) __half g_p1h [NN * 512];
__device__ __align__(16) __half g_p2h [NN * 512];

// pre-converted fp16 weights (padded strides, k' = m*16+f ordering)
__device__ __align__(16) __half g_w16 [80 * 84];   // [o][k'] stride 84
__device__ __align__(16) __half g_wo16[80 * 68];   // [p][u]  stride 68

__device__ __forceinline__ const __half* hsel(int id) {
    switch (id) {
        case 0: return g_x0h;  case 1: return g_xs1h; case 2: return g_xs2h;
        case 3: return g_xs3h; case 4: return g_xs4h; case 5: return g_z2h;
        case 6: return g_z4h;  case 7: return g_p1h;  default: return g_p2h;
    }
}
__device__ __forceinline__ __half* hsel_w(int id) {
    switch (id) {
        case 1: return g_xs1h; case 2: return g_xs2h; case 3: return g_xs3h;
        case 4: return g_xs4h; case 7: return g_p1h;  default: return g_p2h;
    }
}
__device__ __forceinline__ const float* fsel(int id) {
    return (id == 0) ? g_z1 : g_z3;
}

// ---------------- helpers ----------------
__device__ __forceinline__ __half2 h2b(uint32_t u) { return *(__half2*)&u; }
__device__ __forceinline__ float tanh_ap(float x) {
    float r;
    asm("tanh.approx.f32 %0, %1;" : "=f"(r) : "f"(x));
    return r;
}
__device__ __forceinline__ uint32_t packh2(float a, float b) {
    __half2 h = __floats2half2_rn(a, b);
    return *(uint32_t*)&h;
}
__device__ __forceinline__ void mma16816(float* c, uint32_t a0, uint32_t a1, uint32_t a2, uint32_t a3,
                                         uint32_t b0, uint32_t b1) {
    asm volatile("mma.sync.aligned.m16n8k16.row.col.f32.f16.f16.f32 "
        "{%0,%1,%2,%3}, {%4,%5,%6,%7}, {%8,%9}, {%0,%1,%2,%3};"
        : "+f"(c[0]), "+f"(c[1]), "+f"(c[2]), "+f"(c[3])
        : "r"(a0), "r"(a1), "r"(a2), "r"(a3), "r"(b0), "r"(b1));
}

// wide 4-edge gather: 8 elements per thread (uint4), fp16 inner accum, fp32 flush
__device__ __forceinline__ void gather4w(const uint4* __restrict__ x, const int2* se, int i, int j,
                                         float* acc) {
    int2 e0 = se[i], e1 = se[i + 1], e2 = se[i + 2], e3 = se[i + 3];
    uint4 g0 = __ldg(&x[e0.x * 64 + j]);
    uint4 g1 = __ldg(&x[e1.x * 64 + j]);
    uint4 g2 = __ldg(&x[e2.x * 64 + j]);
    uint4 g3 = __ldg(&x[e3.x * 64 + j]);
    __half2 z = __float2half2_rn(0.f);
    __half2 a0 = z, a1 = z, a2 = z, a3 = z;
    __half2 w0 = h2b(e0.y), w1 = h2b(e1.y), w2 = h2b(e2.y), w3 = h2b(e3.y);
    a0 = __hfma2(h2b(g0.x), w0, a0); a1 = __hfma2(h2b(g0.y), w0, a1);
    a2 = __hfma2(h2b(g0.z), w0, a2); a3 = __hfma2(h2b(g0.w), w0, a3);
    a0 = __hfma2(h2b(g1.x), w1, a0); a1 = __hfma2(h2b(g1.y), w1, a1);
    a2 = __hfma2(h2b(g1.z), w1, a2); a3 = __hfma2(h2b(g1.w), w1, a3);
    a0 = __hfma2(h2b(g2.x), w2, a0); a1 = __hfma2(h2b(g2.y), w2, a1);
    a2 = __hfma2(h2b(g2.z), w2, a2); a3 = __hfma2(h2b(g2.w), w2, a3);
    a0 = __hfma2(h2b(g3.x), w3, a0); a1 = __hfma2(h2b(g3.y), w3, a1);
    a2 = __hfma2(h2b(g3.z), w3, a2); a3 = __hfma2(h2b(g3.w), w3, a3);
    float2 f0 = __half22float2(a0), f1 = __half22float2(a1);
    float2 f2 = __half22float2(a2), f3 = __half22float2(a3);
    acc[0] += f0.x; acc[1] += f0.y; acc[2] += f1.x; acc[3] += f1.y;
    acc[4] += f2.x; acc[5] += f2.y; acc[6] += f3.x; acc[7] += f3.y;
}
__device__ __forceinline__ void gather1w(const uint4* __restrict__ x, const int2* se, int i, int j,
                                         float* acc) {
    int2 ed = se[i];
    float v = __half2float(__low2half(h2b(ed.y)));
    uint4 g = __ldg(&x[ed.x * 64 + j]);
    float2 f0 = __half22float2(h2b(g.x)), f1 = __half22float2(h2b(g.y));
    float2 f2 = __half22float2(h2b(g.z)), f3 = __half22float2(h2b(g.w));
    acc[0] += v * f0.x; acc[1] += v * f0.y; acc[2] += v * f1.x; acc[3] += v * f1.y;
    acc[4] += v * f2.x; acc[5] += v * f2.y; acc[6] += v * f3.x; acc[7] += v * f3.y;
}

// ---------------- fused pre: transpose | ELL scatter | weight convert ----------------
#define SCAT_BLKS (2 * NNZT / 512)
__global__ __launch_bounds__(512) void k_pre(const float* __restrict__ y,
        const int* __restrict__ r1, const int* __restrict__ c1, const float* __restrict__ v1,
        const int* __restrict__ r2, const int* __restrict__ c2, const float* __restrict__ v2,
        const float* __restrict__ Wt, const float* __restrict__ Wh, const float* __restrict__ Wo) {
    int t = threadIdx.x;
    if (blockIdx.x < NN) {
        int n = blockIdx.x;
        if (t < 256) {
            int idx2 = t * 2;              // element index b*16+f
            int b = idx2 >> 4, f = idx2 & 15;
            float2 yv = *(const float2*)&y[b * (NN * 16) + n * 16 + f];
            ((__half2*)g_x0h)[n * 256 + t] = __floats2half2_rn(yv.x, yv.y);
        }
    } else if (blockIdx.x < NN + SCAT_BLKS) {
        int gi = (blockIdx.x - NN) * 512 + t;     // covers [0, 2*NNZT)
        int sup = gi >= NNZT;
        int e = sup ? gi - NNZT : gi;
        const int*   r = sup ? r2 : r1;
        const int*   c = sup ? c2 : c1;
        const float* v = sup ? v2 : v1;
        int row = __ldg(&r[e]);
        int p = atomicAdd(&g_len[sup][row], 1);
        if (p < ELLW) {
            __half2 hv = __half2half2(__float2half_rn(__ldg(&v[e])));
            g_ell[sup][row * ELLW + p] = make_int2(__ldg(&c[e]), (int)*(uint32_t*)&hv);
        }
    } else {
        int wi = (blockIdx.x - NN - SCAT_BLKS) * 512 + t;
        if (wi < 6720) {
            int o = wi / 84, kp = wi - o * 84;
            float w = 0.f;
            if (kp < 80) {
                int f = kp & 15, m = kp >> 4;
                int ks = f * 5 + m;
                w = (o < 16) ? Wt[ks * 16 + o] : Wh[ks * 64 + (o - 16)];
            }
            g_w16[wi] = __float2half(w);
        } else if (wi < 6720 + 5440) {
            int wj = wi - 6720;
            int p = wj / 68, u = wj - p * 68;
            g_wo16[wj] = __float2half(u < 64 ? Wo[u * 80 + p] : 0.f);
        }
    }
}

// ---------------- dual-job wide half SpMM: out = al*(S@hsrc) + be*add ----------------
__global__ __launch_bounds__(64) void k_spmm2(
        int hA, int adfA, int adhA, float alA, float beA, int oA,
        int hB, int adfB, int adhB, float alB, float beB, int oB) {
    __shared__ int2 se[ELLW];
    int unit = blockIdx.x >> 12;
    int n = blockIdx.x & (NN - 1);
    int hid = unit ? hB : hA;
    int adf = unit ? adfB : adfA;
    int adh = unit ? adhB : adhA;
    float al = unit ? alB : alA;
    float be = unit ? beB : beA;
    int oid = unit ? oB : oA;

    int cnt = g_len[unit][n]; if (cnt > ELLW) cnt = ELLW;
    if (threadIdx.x < cnt) se[threadIdx.x] = __ldg(&g_ell[unit][n * ELLW + threadIdx.x]);
    __syncthreads();

    int j = threadIdx.x;
    const uint4* __restrict__ x = (const uint4*)hsel(hid);
    float acc[8] = {0.f, 0.f, 0.f, 0.f, 0.f, 0.f, 0.f, 0.f};
    int i = 0;
    for (; i + 4 <= cnt; i += 4) gather4w(x, se, i, j, acc);
    for (; i < cnt; ++i)         gather1w(x, se, i, j, acc);

#pragma unroll
    for (int p = 0; p < 8; p++) acc[p] *= al;
    if (adf >= 0) {
        const float4* ad = (const float4*)fsel(adf);
        float4 a0 = __ldg(&ad[n * 128 + j * 2]);
        float4 a1 = __ldg(&ad[n * 128 + j * 2 + 1]);
        acc[0] += be * a0.x; acc[1] += be * a0.y; acc[2] += be * a0.z; acc[3] += be * a0.w;
        acc[4] += be * a1.x; acc[5] += be * a1.y; acc[6] += be * a1.z; acc[7] += be * a1.w;
    } else if (adh >= 0) {
        uint4 av = __ldg(&((const uint4*)hsel(adh))[n * 64 + j]);
        float2 f0 = __half22float2(h2b(av.x)), f1 = __half22float2(h2b(av.y));
        float2 f2 = __half22float2(h2b(av.z)), f3 = __half22float2(h2b(av.w));
        acc[0] += be * f0.x; acc[1] += be * f0.y; acc[2] += be * f1.x; acc[3] += be * f1.y;
        acc[4] += be * f2.x; acc[5] += be * f2.y; acc[6] += be * f3.x; acc[7] += be * f3.y;
    }
    uint4 o;
    o.x = packh2(acc[0], acc[1]); o.y = packh2(acc[2], acc[3]);
    o.z = packh2(acc[4], acc[5]); o.w = packh2(acc[6], acc[7]);
    ((uint4*)hsel_w(oid))[n * 64 + j] = o;
}

// ---------------- HMMA kernel with in-register c1 forwarding ----------------
// A layout [row = nd*32+b][k' = m*16+f] stride 88; GEMM1 C-fragment == GEMM2 A-fragment.
#define OFF_A   0
#define OFF_W   22528
#define OFF_WO  35968
#define SM_TOT  46848
#define STA 88
#define STW 84
#define STO 68

__global__ __launch_bounds__(256, 3) void k_mma(const float* __restrict__ blat,
                                                const float* __restrict__ bhid) {
    extern __shared__ __align__(16) char dsm[];
    __half* sA   = (__half*)(dsm + OFF_A);
    __half* sW   = (__half*)(dsm + OFF_W);
    __half* sWo  = (__half*)(dsm + OFF_WO);

    int tid = threadIdx.x;
    int n0 = blockIdx.x * 4;

    // stage sA: 5 mirrors -> [row][k'], one LDG.128 + one aligned STS.128 per unit
    for (int e = tid; e < 1280; e += 256) {
        int m = e >> 8, idx = e & 255;
        int nd = idx >> 6, j = idx & 63;
        uint4 gv = __ldg(&((const uint4*)hsel(m))[(n0 + nd) * 64 + j]);
        int b = j >> 1, f0 = (j & 1) * 8;
        int row = nd * 32 + b;
        *(uint4*)&sA[row * STA + m * 16 + f0] = gv;
    }
    // stage weights: flat uint4 memcpy
    for (int e = tid; e < 840; e += 256) ((uint4*)sW)[e]  = ((const uint4*)g_w16)[e];
    for (int e = tid; e < 680; e += 256) ((uint4*)sWo)[e] = ((const uint4*)g_wo16)[e];
    __syncthreads();

    int w = tid >> 5, t = tid & 31;
    int g = t >> 2, q = t & 3;
    int rowA = w * 16 + g;
    const __half* aBase = sA + rowA * STA;

    // GEMM1: C[128x80] = A @ W^T (fp32 accum)
    float acc[10][4];
#pragma unroll
    for (int nt = 0; nt < 10; nt++)
        for (int p = 0; p < 4; p++) acc[nt][p] = 0.f;
#pragma unroll
    for (int kt = 0; kt < 5; kt++) {
        int k0 = kt * 16 + q * 2;
        uint32_t a0 = *(const uint32_t*)(aBase + k0);
        uint32_t a1 = *(const uint32_t*)(aBase + 8 * STA + k0);
        uint32_t a2 = *(const uint32_t*)(aBase + k0 + 8);
        uint32_t a3 = *(const uint32_t*)(aBase + 8 * STA + k0 + 8);
#pragma unroll
        for (int nt = 0; nt < 10; nt++) {
            const __half* bb = sW + (nt * 8 + g) * STW + k0;
            uint32_t b0 = *(const uint32_t*)bb;
            uint32_t b1 = *(const uint32_t*)(bb + 8);
            mma16816(acc[nt], a0, a1, a2, a3, b0, b1);
        }
    }
    // theta epilogue (nt = 0,1 -> o < 16)
#pragma unroll
    for (int nt = 0; nt < 2; nt++) {
        int o = nt * 8 + q * 2;
        float bl0 = blat[o], bl1 = blat[o + 1];
#pragma unroll
        for (int hf = 0; hf < 2; hf++) {
            int row = rowA + hf * 8;
            int n = n0 + (row >> 5), b = row & 31;
            float2 tv;
            tv.x = 0.5f + 0.5f * tanh_ap(0.5f * (acc[nt][hf * 2]     + bl0));
            tv.y = 0.5f + 0.5f * tanh_ap(0.5f * (acc[nt][hf * 2 + 1] + bl1));
            *(float2*)&g_theta[n * 512 + b * 16 + o] = tv;
        }
    }
    // c1: tanh + pack IN REGISTERS — GEMM1 C-fragment == GEMM2 A-fragment
    uint32_t cf[8][2];
#pragma unroll
    for (int nt = 2; nt < 10; nt++) {
        int u = (nt - 2) * 8 + q * 2;
        float bh0 = bhid[u], bh1 = bhid[u + 1];
        cf[nt - 2][0] = packh2(tanh_ap(acc[nt][0] + bh0), tanh_ap(acc[nt][1] + bh1));
        cf[nt - 2][1] = packh2(tanh_ap(acc[nt][2] + bh0), tanh_ap(acc[nt][3] + bh1));
    }

    // GEMM2: Z[128x80] = C1[128x64] @ Wo^T (A from registers, no smem, no sync)
    float acc2[10][4];
#pragma unroll
    for (int nt = 0; nt < 10; nt++)
        for (int p = 0; p < 4; p++) acc2[nt][p] = 0.f;
#pragma unroll
    for (int kt = 0; kt < 4; kt++) {
        int k0 = kt * 16 + q * 2;
        uint32_t a0 = cf[2 * kt][0];
        uint32_t a1 = cf[2 * kt][1];
        uint32_t a2 = cf[2 * kt + 1][0];
        uint32_t a3 = cf[2 * kt + 1][1];
#pragma unroll
        for (int nt = 0; nt < 10; nt++) {
            const __half* bb = sWo + (nt * 8 + g) * STO + k0;
            uint32_t b0 = *(const uint32_t*)bb;
            uint32_t b1 = *(const uint32_t*)(bb + 8);
            mma16816(acc2[nt], a0, a1, a2, a3, b0, b1);
        }
    }
    // epilogue 2: zc = z0-z2-z4, z1, z3, fp16 mirrors for z2/z4
    {
        int o0 = q * 2, o1 = 8 + q * 2;
#pragma unroll
        for (int hf = 0; hf < 2; hf++) {
            int row = rowA + hf * 8;
            int n = n0 + (row >> 5), b = row & 31;
            int base = n * 512 + b * 16;
            int h2 = hf * 2;
            float2 zc0, zc1;
            zc0.x = acc2[0][h2]     - acc2[4][h2]     - acc2[8][h2];
            zc0.y = acc2[0][h2 + 1] - acc2[4][h2 + 1] - acc2[8][h2 + 1];
            zc1.x = acc2[1][h2]     - acc2[5][h2]     - acc2[9][h2];
            zc1.y = acc2[1][h2 + 1] - acc2[5][h2 + 1] - acc2[9][h2 + 1];
            *(float2*)&g_zc[base + o0] = zc0;
            *(float2*)&g_zc[base + o1] = zc1;
            *(float2*)&g_z1[base + o0] = make_float2(acc2[2][h2], acc2[2][h2 + 1]);
            *(float2*)&g_z1[base + o1] = make_float2(acc2[3][h2], acc2[3][h2 + 1]);
            *(float2*)&g_z3[base + o0] = make_float2(acc2[6][h2], acc2[6][h2 + 1]);
            *(float2*)&g_z3[base + o1] = make_float2(acc2[7][h2], acc2[7][h2 + 1]);
            *(uint32_t*)&g_z2h[base + o0] = packh2(acc2[4][h2], acc2[4][h2 + 1]);
            *(uint32_t*)&g_z2h[base + o1] = packh2(acc2[5][h2], acc2[5][h2 + 1]);
            *(uint32_t*)&g_z4h[base + o0] = packh2(acc2[8][h2], acc2[8][h2 + 1]);
            *(uint32_t*)&g_z4h[base + o1] = packh2(acc2[9][h2], acc2[9][h2 + 1]);
        }
    }
}

// ---------------- final: S1@p1h + S2@p2h + zc + b -> -theta*tanh, direct store ----------------
__global__ __launch_bounds__(64) void k_final(const float* __restrict__ blat, float* __restrict__ out) {
    __shared__ int2 se1[ELLW], se2[ELLW];
    int n = blockIdx.x, j = threadIdx.x;

    int c1n = g_len[0][n]; if (c1n > ELLW) c1n = ELLW;
    int c2n = g_len[1][n]; if (c2n > ELLW) c2n = ELLW;
    if (j < c1n) se1[j] = __ldg(&g_ell[0][n * ELLW + j]);
    if (j < c2n) se2[j] = __ldg(&g_ell[1][n * ELLW + j]);
    __syncthreads();
    if (j < 2) g_len[j][n] = 0;     // reset for next pipeline run

    const uint4* __restrict__ xp1 = (const uint4*)g_p1h;
    const uint4* __restrict__ xp2 = (const uint4*)g_p2h;
    float acc[8] = {0.f, 0.f, 0.f, 0.f, 0.f, 0.f, 0.f, 0.f};

    int i = 0;
    for (; i + 4 <= c1n; i += 4) gather4w(xp1, se1, i, j, acc);
    for (; i < c1n; ++i)         gather1w(xp1, se1, i, j, acc);
    i = 0;
    for (; i + 4 <= c2n; i += 4) gather4w(xp2, se2, i, j, acc);
    for (; i < c2n; ++i)         gather1w(xp2, se2, i, j, acc);

    int idx = n * 128 + j * 2;
    float4 tc0 = ((const float4*)g_zc)[idx];
    float4 tc1 = ((const float4*)g_zc)[idx + 1];
    float4 tt0 = ((const float4*)g_theta)[idx];
    float4 tt1 = ((const float4*)g_theta)[idx + 1];

    int b = j >> 1, o0 = (j & 1) * 8;
    float4 bl0 = *(const float4*)&blat[o0];
    float4 bl1 = *(const float4*)&blat[o0 + 4];

    float4 r0, r1;
    r0.x = -tt0.x * tanh_ap(acc[0] + tc0.x + bl0.x);
    r0.y = -tt0.y * tanh_ap(acc[1] + tc0.y + bl0.y);
    r0.z = -tt0.z * tanh_ap(acc[2] + tc0.z + bl0.z);
    r0.w = -tt0.w * tanh_ap(acc[3] + tc0.w + bl0.w);
    r1.x = -tt1.x * tanh_ap(acc[4] + tc1.x + bl1.x);
    r1.y = -tt1.y * tanh_ap(acc[5] + tc1.y + bl1.y);
    r1.z = -tt1.z * tanh_ap(acc[6] + tc1.z + bl1.z);
    r1.w = -tt1.w * tanh_ap(acc[7] + tc1.w + bl1.w);
    float* dst = out + b * (NN * 16) + n * 16 + o0;
    *(float4*)dst = r0;
    *(float4*)(dst + 4) = r1;
}

// ---------------- host launcher ----------------
extern "C" void kernel_launch(void* const* d_in, const int* in_sizes, int n_in,
                              void* d_out, int out_size) {
    (void)in_sizes; (void)n_in; (void)out_size;
    const float* y    = (const float*)d_in[1];
    const float* Wt   = (const float*)d_in[2];
    const float* blat = (const float*)d_in[3];
    const float* Wh   = (const float*)d_in[4];
    const float* bhid = (const float*)d_in[5];
    const float* Wo   = (const float*)d_in[6];
    const int*   r1   = (const int*)d_in[7];
    const int*   c1   = (const int*)d_in[8];
    const float* v1   = (const float*)d_in[9];
    const int*   r2   = (const int*)d_in[10];
    const int*   c2   = (const int*)d_in[11];
    const float* v2   = (const float*)d_in[12];
    float* out = (float*)d_out;

    cudaFuncSetAttribute(k_mma, cudaFuncAttributeMaxDynamicSharedMemorySize, SM_TOT);

    // fused transpose + ELL scatter + weight convert
    k_pre<<<NN + SCAT_BLKS + 24, 512>>>(y, r1, c1, v1, r2, c2, v2, Wt, Wh, Wo);

    // hop1: xs1h = S1@x0h ; xs3h = S2@x0h
    k_spmm2<<<2 * NN, 64>>>(0, -1, -1, 1.f, 0.f, 1,   0, -1, -1, 1.f, 0.f, 3);
    // hop2: xs2h = 2*S1@xs1h - x0h ; xs4h = 2*S2@xs3h - x0h
    k_spmm2<<<2 * NN, 64>>>(1, -1, 0, 2.f, -1.f, 2,   3, -1, 0, 2.f, -1.f, 4);

    // HMMA with register-forwarded c1   (profiled slot)
    k_mma<<<NN / 4, 256, SM_TOT>>>(blat, bhid);

    // p1h = z1 + 2*(S1@z2h) ; p2h = z3 + 2*(S2@z4h)
    k_spmm2<<<2 * NN, 64>>>(5, 0, -1, 2.f, 1.f, 7,   6, 1, -1, 2.f, 1.f, 8);

    // final: second-hop gathers + zc + tanh + gate + direct transposed store
    k_final<<<NN, 64>>>(blat, out);
}

// round 17
// speedup vs baseline: 1.5136x; 1.0035x over previous
#include <cuda_runtime.h>
#include <cuda_fp16.h>
#include <math.h>
#include <cstdint>

#define NN    4096
#define NNZT  65536
#define ELLW  64

// ---------------- scratch (device globals) ----------------
__device__ int   g_len[2][NN];            // starts 0 (static); k_final re-zeroes
__device__ __align__(16) int2 g_ell[2][NN * ELLW];   // (col, val as duplicated half2)

// fp32 canonical, layout [n][b*16+o]
__device__ __align__(16) float g_zc[NN * 512];       // z0 - z2 - z4

// fp16 buffers, layout [n][b*16+f]
__device__ __align__(16) __half g_x0h [NN * 512];
__device__ __align__(16) __half g_xs1h[NN * 512];
__device__ __align__(16) __half g_xs2h[NN * 512];
__device__ __align__(16) __half g_xs3h[NN * 512];
__device__ __align__(16) __half g_xs4h[NN * 512];
__device__ __align__(16) __half g_z2h [NN * 512];
__device__ __align__(16) __half g_z4h [NN * 512];
__device__ __align__(16) __half g_p1h [NN * 512];
__device__ __align__(16) __half g_p2h [NN * 512];
__device__ __align__(16) __half g_z1h [NN * 512];
__device__ __align__(16) __half g_z3h [NN * 512];
__device__ __align__(16) __half g_thetah[NN * 512];

// pre-converted fp16 weights (padded strides, k' = m*16+f ordering)
__device__ __align__(16) __half g_w16 [80 * 84];   // [o][k'] stride 84
__device__ __align__(16) __half g_wo16[80 * 68];   // [p][u]  stride 68

__device__ __forceinline__ const __half* hsel(int id) {
    switch (id) {
        case 0: return g_x0h;  case 1: return g_xs1h; case 2: return g_xs2h;
        case 3: return g_xs3h; case 4: return g_xs4h; case 5: return g_z2h;
        case 6: return g_z4h;  case 7: return g_p1h;  case 8: return g_p2h;
        case 9: return g_z1h;  default: return g_z3h;
    }
}
__device__ __forceinline__ __half* hsel_w(int id) {
    switch (id) {
        case 1: return g_xs1h; case 2: return g_xs2h; case 3: return g_xs3h;
        case 4: return g_xs4h; case 7: return g_p1h;  default: return g_p2h;
    }
}

// ---------------- helpers ----------------
__device__ __forceinline__ __half2 h2b(uint32_t u) { return *(__half2*)&u; }
__device__ __forceinline__ float tanh_ap(float x) {
    float r;
    asm("tanh.approx.f32 %0, %1;" : "=f"(r) : "f"(x));
    return r;
}
__device__ __forceinline__ uint32_t packh2(float a, float b) {
    __half2 h = __floats2half2_rn(a, b);
    return *(uint32_t*)&h;
}
__device__ __forceinline__ void mma16816(float* c, uint32_t a0, uint32_t a1, uint32_t a2, uint32_t a3,
                                         uint32_t b0, uint32_t b1) {
    asm volatile("mma.sync.aligned.m16n8k16.row.col.f32.f16.f16.f32 "
        "{%0,%1,%2,%3}, {%4,%5,%6,%7}, {%8,%9}, {%0,%1,%2,%3};"
        : "+f"(c[0]), "+f"(c[1]), "+f"(c[2]), "+f"(c[3])
        : "r"(a0), "r"(a1), "r"(a2), "r"(a3), "r"(b0), "r"(b1));
}

// wide 4-edge gather: 8 elements per thread (uint4), fp16 inner accum, fp32 flush
__device__ __forceinline__ void gather4w(const uint4* __restrict__ x, const int2* se, int i, int j,
                                         float* acc) {
    int2 e0 = se[i], e1 = se[i + 1], e2 = se[i + 2], e3 = se[i + 3];
    uint4 g0 = __ldg(&x[e0.x * 64 + j]);
    uint4 g1 = __ldg(&x[e1.x * 64 + j]);
    uint4 g2 = __ldg(&x[e2.x * 64 + j]);
    uint4 g3 = __ldg(&x[e3.x * 64 + j]);
    __half2 z = __float2half2_rn(0.f);
    __half2 a0 = z, a1 = z, a2 = z, a3 = z;
    __half2 w0 = h2b(e0.y), w1 = h2b(e1.y), w2 = h2b(e2.y), w3 = h2b(e3.y);
    a0 = __hfma2(h2b(g0.x), w0, a0); a1 = __hfma2(h2b(g0.y), w0, a1);
    a2 = __hfma2(h2b(g0.z), w0, a2); a3 = __hfma2(h2b(g0.w), w0, a3);
    a0 = __hfma2(h2b(g1.x), w1, a0); a1 = __hfma2(h2b(g1.y), w1, a1);
    a2 = __hfma2(h2b(g1.z), w1, a2); a3 = __hfma2(h2b(g1.w), w1, a3);
    a0 = __hfma2(h2b(g2.x), w2, a0); a1 = __hfma2(h2b(g2.y), w2, a1);
    a2 = __hfma2(h2b(g2.z), w2, a2); a3 = __hfma2(h2b(g2.w), w2, a3);
    a0 = __hfma2(h2b(g3.x), w3, a0); a1 = __hfma2(h2b(g3.y), w3, a1);
    a2 = __hfma2(h2b(g3.z), w3, a2); a3 = __hfma2(h2b(g3.w), w3, a3);
    float2 f0 = __half22float2(a0), f1 = __half22float2(a1);
    float2 f2 = __half22float2(a2), f3 = __half22float2(a3);
    acc[0] += f0.x; acc[1] += f0.y; acc[2] += f1.x; acc[3] += f1.y;
    acc[4] += f2.x; acc[5] += f2.y; acc[6] += f3.x; acc[7] += f3.y;
}
__device__ __forceinline__ void gather1w(const uint4* __restrict__ x, const int2* se, int i, int j,
                                         float* acc) {
    int2 ed = se[i];
    float v = __half2float(__low2half(h2b(ed.y)));
    uint4 g = __ldg(&x[ed.x * 64 + j]);
    float2 f0 = __half22float2(h2b(g.x)), f1 = __half22float2(h2b(g.y));
    float2 f2 = __half22float2(h2b(g.z)), f3 = __half22float2(h2b(g.w));
    acc[0] += v * f0.x; acc[1] += v * f0.y; acc[2] += v * f1.x; acc[3] += v * f1.y;
    acc[4] += v * f2.x; acc[5] += v * f2.y; acc[6] += v * f3.x; acc[7] += v * f3.y;
}

// ---------------- fused pre: transpose | ELL scatter | weight convert ----------------
#define SCAT_BLKS (2 * NNZT / 512)
__global__ __launch_bounds__(512) void k_pre(const float* __restrict__ y,
        const int* __restrict__ r1, const int* __restrict__ c1, const float* __restrict__ v1,
        const int* __restrict__ r2, const int* __restrict__ c2, const float* __restrict__ v2,
        const float* __restrict__ Wt, const float* __restrict__ Wh, const float* __restrict__ Wo) {
    int t = threadIdx.x;
    if (blockIdx.x < NN) {
        int n = blockIdx.x;
        if (t < 256) {
            int idx2 = t * 2;              // element index b*16+f
            int b = idx2 >> 4, f = idx2 & 15;
            float2 yv = *(const float2*)&y[b * (NN * 16) + n * 16 + f];
            ((__half2*)g_x0h)[n * 256 + t] = __floats2half2_rn(yv.x, yv.y);
        }
    } else if (blockIdx.x < NN + SCAT_BLKS) {
        int gi = (blockIdx.x - NN) * 512 + t;     // covers [0, 2*NNZT)
        int sup = gi >= NNZT;
        int e = sup ? gi - NNZT : gi;
        const int*   r = sup ? r2 : r1;
        const int*   c = sup ? c2 : c1;
        const float* v = sup ? v2 : v1;
        int row = __ldg(&r[e]);
        int p = atomicAdd(&g_len[sup][row], 1);
        if (p < ELLW) {
            __half2 hv = __half2half2(__float2half_rn(__ldg(&v[e])));
            g_ell[sup][row * ELLW + p] = make_int2(__ldg(&c[e]), (int)*(uint32_t*)&hv);
        }
    } else {
        int wi = (blockIdx.x - NN - SCAT_BLKS) * 512 + t;
        if (wi < 6720) {
            int o = wi / 84, kp = wi - o * 84;
            float w = 0.f;
            if (kp < 80) {
                int f = kp & 15, m = kp >> 4;
                int ks = f * 5 + m;
                w = (o < 16) ? Wt[ks * 16 + o] : Wh[ks * 64 + (o - 16)];
            }
            g_w16[wi] = __float2half(w);
        } else if (wi < 6720 + 5440) {
            int wj = wi - 6720;
            int p = wj / 68, u = wj - p * 68;
            g_wo16[wj] = __float2half(u < 64 ? Wo[u * 80 + p] : 0.f);
        }
    }
}

// ---------------- dual-job wide half SpMM: out = al*(S@hsrc) + be*hadd ----------------
__global__ __launch_bounds__(64) void k_spmm2(
        int hA, int adhA, float alA, float beA, int oA,
        int hB, int adhB, float alB, float beB, int oB) {
    __shared__ int2 se[ELLW];
    int unit = blockIdx.x >> 12;
    int n = blockIdx.x & (NN - 1);
    int hid = unit ? hB : hA;
    int adh = unit ? adhB : adhA;
    float al = unit ? alB : alA;
    float be = unit ? beB : beA;
    int oid = unit ? oB : oA;

    int cnt = g_len[unit][n]; if (cnt > ELLW) cnt = ELLW;
    if (threadIdx.x < cnt) se[threadIdx.x] = __ldg(&g_ell[unit][n * ELLW + threadIdx.x]);
    __syncthreads();

    int j = threadIdx.x;
    const uint4* __restrict__ x = (const uint4*)hsel(hid);
    float acc[8] = {0.f, 0.f, 0.f, 0.f, 0.f, 0.f, 0.f, 0.f};
    int i = 0;
    for (; i + 4 <= cnt; i += 4) gather4w(x, se, i, j, acc);
    for (; i < cnt; ++i)         gather1w(x, se, i, j, acc);

#pragma unroll
    for (int p = 0; p < 8; p++) acc[p] *= al;
    if (adh >= 0) {
        uint4 av = __ldg(&((const uint4*)hsel(adh))[n * 64 + j]);
        float2 f0 = __half22float2(h2b(av.x)), f1 = __half22float2(h2b(av.y));
        float2 f2 = __half22float2(h2b(av.z)), f3 = __half22float2(h2b(av.w));
        acc[0] += be * f0.x; acc[1] += be * f0.y; acc[2] += be * f1.x; acc[3] += be * f1.y;
        acc[4] += be * f2.x; acc[5] += be * f2.y; acc[6] += be * f3.x; acc[7] += be * f3.y;
    }
    uint4 o;
    o.x = packh2(acc[0], acc[1]); o.y = packh2(acc[2], acc[3]);
    o.z = packh2(acc[4], acc[5]); o.w = packh2(acc[6], acc[7]);
    ((uint4*)hsel_w(oid))[n * 64 + j] = o;
}

// ---------------- HMMA kernel: 2 nodes per block, 128 threads, 6 CTAs/SM ----------------
// A layout [row = nd*32+b][k' = m*16+f] stride 88; GEMM1 C-fragment == GEMM2 A-fragment.
#define OFF_A   0
#define OFF_W   11264
#define OFF_WO  24704
#define SM_TOT  35584
#define STA 88
#define STW 84
#define STO 68

__global__ __launch_bounds__(128, 6) void k_mma(const float* __restrict__ blat,
                                                const float* __restrict__ bhid) {
    extern __shared__ __align__(16) char dsm[];
    __half* sA   = (__half*)(dsm + OFF_A);
    __half* sW   = (__half*)(dsm + OFF_W);
    __half* sWo  = (__half*)(dsm + OFF_WO);

    int tid = threadIdx.x;
    int n0 = blockIdx.x * 2;

    // stage sA: 5 mirrors x 2 nodes -> [row][k'], one LDG.128 + one STS.128 per unit
    for (int e = tid; e < 640; e += 128) {
        int m = e >> 7, idx = e & 127;
        int nd = idx >> 6, j = idx & 63;
        uint4 gv = __ldg(&((const uint4*)hsel(m))[(n0 + nd) * 64 + j]);
        int b = j >> 1, f0 = (j & 1) * 8;
        int row = nd * 32 + b;
        *(uint4*)&sA[row * STA + m * 16 + f0] = gv;
    }
    // stage weights: flat uint4 memcpy
    for (int e = tid; e < 840; e += 128) ((uint4*)sW)[e]  = ((const uint4*)g_w16)[e];
    for (int e = tid; e < 680; e += 128) ((uint4*)sWo)[e] = ((const uint4*)g_wo16)[e];
    __syncthreads();

    int w = tid >> 5, t = tid & 31;
    int g = t >> 2, q = t & 3;
    int rowA = w * 16 + g;
    const __half* aBase = sA + rowA * STA;

    // GEMM1: C[64x80] = A @ W^T (fp32 accum)
    float acc[10][4];
#pragma unroll
    for (int nt = 0; nt < 10; nt++)
        for (int p = 0; p < 4; p++) acc[nt][p] = 0.f;
#pragma unroll
    for (int kt = 0; kt < 5; kt++) {
        int k0 = kt * 16 + q * 2;
        uint32_t a0 = *(const uint32_t*)(aBase + k0);
        uint32_t a1 = *(const uint32_t*)(aBase + 8 * STA + k0);
        uint32_t a2 = *(const uint32_t*)(aBase + k0 + 8);
        uint32_t a3 = *(const uint32_t*)(aBase + 8 * STA + k0 + 8);
#pragma unroll
        for (int nt = 0; nt < 10; nt++) {
            const __half* bb = sW + (nt * 8 + g) * STW + k0;
            uint32_t b0 = *(const uint32_t*)bb;
            uint32_t b1 = *(const uint32_t*)(bb + 8);
            mma16816(acc[nt], a0, a1, a2, a3, b0, b1);
        }
    }
    // theta epilogue (nt = 0,1 -> o < 16), fp16 store
#pragma unroll
    for (int nt = 0; nt < 2; nt++) {
        int o = nt * 8 + q * 2;
        float bl0 = blat[o], bl1 = blat[o + 1];
#pragma unroll
        for (int hf = 0; hf < 2; hf++) {
            int row = rowA + hf * 8;
            int n = n0 + (row >> 5), b = row & 31;
            float t0 = 0.5f + 0.5f * tanh_ap(0.5f * (acc[nt][hf * 2]     + bl0));
            float t1 = 0.5f + 0.5f * tanh_ap(0.5f * (acc[nt][hf * 2 + 1] + bl1));
            *(uint32_t*)&g_thetah[n * 512 + b * 16 + o] = packh2(t0, t1);
        }
    }
    // c1: tanh + pack IN REGISTERS — GEMM1 C-fragment == GEMM2 A-fragment
    uint32_t cf[8][2];
#pragma unroll
    for (int nt = 2; nt < 10; nt++) {
        int u = (nt - 2) * 8 + q * 2;
        float bh0 = bhid[u], bh1 = bhid[u + 1];
        cf[nt - 2][0] = packh2(tanh_ap(acc[nt][0] + bh0), tanh_ap(acc[nt][1] + bh1));
        cf[nt - 2][1] = packh2(tanh_ap(acc[nt][2] + bh0), tanh_ap(acc[nt][3] + bh1));
    }

    // GEMM2: Z[64x80] = C1[64x64] @ Wo^T (A from registers, no smem, no sync)
    float acc2[10][4];
#pragma unroll
    for (int nt = 0; nt < 10; nt++)
        for (int p = 0; p < 4; p++) acc2[nt][p] = 0.f;
#pragma unroll
    for (int kt = 0; kt < 4; kt++) {
        int k0 = kt * 16 + q * 2;
        uint32_t a0 = cf[2 * kt][0];
        uint32_t a1 = cf[2 * kt][1];
        uint32_t a2 = cf[2 * kt + 1][0];
        uint32_t a3 = cf[2 * kt + 1][1];
#pragma unroll
        for (int nt = 0; nt < 10; nt++) {
            const __half* bb = sWo + (nt * 8 + g) * STO + k0;
            uint32_t b0 = *(const uint32_t*)bb;
            uint32_t b1 = *(const uint32_t*)(bb + 8);
            mma16816(acc2[nt], a0, a1, a2, a3, b0, b1);
        }
    }
    // epilogue 2: zc = z0-z2-z4 (fp32), z1h/z3h/z2h/z4h (fp16)
    {
        int o0 = q * 2, o1 = 8 + q * 2;
#pragma unroll
        for (int hf = 0; hf < 2; hf++) {
            int row = rowA + hf * 8;
            int n = n0 + (row >> 5), b = row & 31;
            int base = n * 512 + b * 16;
            int h2 = hf * 2;
            float2 zc0, zc1;
            zc0.x = acc2[0][h2]     - acc2[4][h2]     - acc2[8][h2];
            zc0.y = acc2[0][h2 + 1] - acc2[4][h2 + 1] - acc2[8][h2 + 1];
            zc1.x = acc2[1][h2]     - acc2[5][h2]     - acc2[9][h2];
            zc1.y = acc2[1][h2 + 1] - acc2[5][h2 + 1] - acc2[9][h2 + 1];
            *(float2*)&g_zc[base + o0] = zc0;
            *(float2*)&g_zc[base + o1] = zc1;
            *(uint32_t*)&g_z1h[base + o0] = packh2(acc2[2][h2], acc2[2][h2 + 1]);
            *(uint32_t*)&g_z1h[base + o1] = packh2(acc2[3][h2], acc2[3][h2 + 1]);
            *(uint32_t*)&g_z3h[base + o0] = packh2(acc2[6][h2], acc2[6][h2 + 1]);
            *(uint32_t*)&g_z3h[base + o1] = packh2(acc2[7][h2], acc2[7][h2 + 1]);
            *(uint32_t*)&g_z2h[base + o0] = packh2(acc2[4][h2], acc2[4][h2 + 1]);
            *(uint32_t*)&g_z2h[base + o1] = packh2(acc2[5][h2], acc2[5][h2 + 1]);
            *(uint32_t*)&g_z4h[base + o0] = packh2(acc2[8][h2], acc2[8][h2 + 1]);
            *(uint32_t*)&g_z4h[base + o1] = packh2(acc2[9][h2], acc2[9][h2 + 1]);
        }
    }
}

// ---------------- final: S1@p1h + S2@p2h + zc + b -> -theta*tanh, direct store ----------------
__global__ __launch_bounds__(64) void k_final(const float* __restrict__ blat, float* __restrict__ out) {
    __shared__ int2 se1[ELLW], se2[ELLW];
    int n = blockIdx.x, j = threadIdx.x;

    int c1n = g_len[0][n]; if (c1n > ELLW) c1n = ELLW;
    int c2n = g_len[1][n]; if (c2n > ELLW) c2n = ELLW;
    if (j < c1n) se1[j] = __ldg(&g_ell[0][n * ELLW + j]);
    if (j < c2n) se2[j] = __ldg(&g_ell[1][n * ELLW + j]);
    __syncthreads();
    if (j < 2) g_len[j][n] = 0;     // reset for next pipeline run

    const uint4* __restrict__ xp1 = (const uint4*)g_p1h;
    const uint4* __restrict__ xp2 = (const uint4*)g_p2h;
    float acc[8] = {0.f, 0.f, 0.f, 0.f, 0.f, 0.f, 0.f, 0.f};

    int i = 0;
    for (; i + 4 <= c1n; i += 4) gather4w(xp1, se1, i, j, acc);
    for (; i < c1n; ++i)         gather1w(xp1, se1, i, j, acc);
    i = 0;
    for (; i + 4 <= c2n; i += 4) gather4w(xp2, se2, i, j, acc);
    for (; i < c2n; ++i)         gather1w(xp2, se2, i, j, acc);

    int idx = n * 128 + j * 2;
    float4 tc0 = ((const float4*)g_zc)[idx];
    float4 tc1 = ((const float4*)g_zc)[idx + 1];
    uint4 tth = __ldg(&((const uint4*)g_thetah)[n * 64 + j]);
    float2 t0 = __half22float2(h2b(tth.x)), t1 = __half22float2(h2b(tth.y));
    float2 t2 = __half22float2(h2b(tth.z)), t3 = __half22float2(h2b(tth.w));

    int b = j >> 1, o0 = (j & 1) * 8;
    float4 bl0 = *(const float4*)&blat[o0];
    float4 bl1 = *(const float4*)&blat[o0 + 4];

    float4 r0, r1;
    r0.x = -t0.x * tanh_ap(acc[0] + tc0.x + bl0.x);
    r0.y = -t0.y * tanh_ap(acc[1] + tc0.y + bl0.y);
    r0.z = -t1.x * tanh_ap(acc[2] + tc0.z + bl0.z);
    r0.w = -t1.y * tanh_ap(acc[3] + tc0.w + bl0.w);
    r1.x = -t2.x * tanh_ap(acc[4] + tc1.x + bl1.x);
    r1.y = -t2.y * tanh_ap(acc[5] + tc1.y + bl1.y);
    r1.z = -t3.x * tanh_ap(acc[6] + tc1.z + bl1.z);
    r1.w = -t3.y * tanh_ap(acc[7] + tc1.w + bl1.w);
    float* dst = out + b * (NN * 16) + n * 16 + o0;
    *(float4*)dst = r0;
    *(float4*)(dst + 4) = r1;
}

// ---------------- host launcher ----------------
extern "C" void kernel_launch(void* const* d_in, const int* in_sizes, int n_in,
                              void* d_out, int out_size) {
    (void)in_sizes; (void)n_in; (void)out_size;
    const float* y    = (const float*)d_in[1];
    const float* Wt   = (const float*)d_in[2];
    const float* blat = (const float*)d_in[3];
    const float* Wh   = (const float*)d_in[4];
    const float* bhid = (const float*)d_in[5];
    const float* Wo   = (const float*)d_in[6];
    const int*   r1   = (const int*)d_in[7];
    const int*   c1   = (const int*)d_in[8];
    const float* v1   = (const float*)d_in[9];
    const int*   r2   = (const int*)d_in[10];
    const int*   c2   = (const int*)d_in[11];
    const float* v2   = (const float*)d_in[12];
    float* out = (float*)d_out;

    cudaFuncSetAttribute(k_mma, cudaFuncAttributeMaxDynamicSharedMemorySize, SM_TOT);

    // fused transpose + ELL scatter + weight convert
    k_pre<<<NN + SCAT_BLKS + 24, 512>>>(y, r1, c1, v1, r2, c2, v2, Wt, Wh, Wo);

    // hop1: xs1h = S1@x0h ; xs3h = S2@x0h
    k_spmm2<<<2 * NN, 64>>>(0, -1, 1.f, 0.f, 1,   0, -1, 1.f, 0.f, 3);
    // hop2: xs2h = 2*S1@xs1h - x0h ; xs4h = 2*S2@xs3h - x0h
    k_spmm2<<<2 * NN, 64>>>(1, 0, 2.f, -1.f, 2,   3, 0, 2.f, -1.f, 4);

    // HMMA, 2-node blocks, 6 CTAs/SM   (profiled slot)
    k_mma<<<NN / 2, 128, SM_TOT>>>(blat, bhid);

    // p1h = z1h + 2*(S1@z2h) ; p2h = z3h + 2*(S2@z4h)
    k_spmm2<<<2 * NN, 64>>>(5, 9, 2.f, 1.f, 7,   6, 10, 2.f, 1.f, 8);

    // final: second-hop gathers + zc + tanh + gate + direct transposed store
    k_final<<<NN, 64>>>(blat, out);
}